// round 10
// baseline (speedup 1.0000x reference)
#include <cuda_runtime.h>
#include <cstdint>

// Problem constants (fixed by the reference)
#define NN    4096     // nodes
#define INF_  128      // input features
#define OUTF  32       // output features per head
#define NH    4        // heads
#define NC    128      // NH*OUTF

// Attention tiling
#define ITILE  64                 // i-rows per block
#define JSPLIT 8                  // j-range splits (additive partial softmax)
#define JCHUNK (NN / JSPLIT)      // 512
#define JSTEP  32                 // j's per round
#define NROUND (JCHUNK / JSTEP)   // 16

#define LOG2E 1.4426950408889634f
#define WXS_STRIDE 136            // 128 + 8 pad: B-frag reads bank-conflict-free

// ---------------- scratch (device globals; no allocation allowed) ----------------
__device__ __align__(16) float g_Wx[NN * NC];            // 2 MB
__device__ __align__(16) float g_es[NN * NH];            // e_src * log2e
__device__ __align__(16) float g_ed[NN * NH];            // e_dst * log2e
__device__ __align__(16) float g_nump[JSPLIT][NN * NC];  // 16 MB partial numerators
__device__ __align__(16) float g_Zp[JSPLIT][NN * NH];    // partial denominators

// ---------------- helpers ----------------
__device__ __forceinline__ uint32_t cvt_tf32(float v) {
    uint32_t r;
    asm("cvt.rna.tf32.f32 %0, %1;" : "=r"(r) : "f"(v));
    return r;
}
// P = mask * 2^(leaky(s)); s already in log2 domain
__device__ __forceinline__ float pval(float s, uint32_t bit) {
    float lk = fmaxf(s, 0.2f * s);
    float e;
    asm("ex2.approx.f32 %0, %1;" : "=f"(e) : "f"(lk));
    return bit ? e : 0.0f;
}
// m16n8k8 tf32 HMMA (sm_80+ baseline PTX; works on plain sm_100)
__device__ __forceinline__ void mma8(float* d, uint32_t a0, uint32_t a1,
                                     uint32_t a2, uint32_t a3,
                                     uint32_t b0, uint32_t b1) {
    asm volatile(
        "mma.sync.aligned.m16n8k8.row.col.f32.tf32.tf32.f32 "
        "{%0,%1,%2,%3}, {%4,%5,%6,%7}, {%8,%9}, {%0,%1,%2,%3};"
        : "+f"(d[0]), "+f"(d[1]), "+f"(d[2]), "+f"(d[3])
        : "r"(a0), "r"(a1), "r"(a2), "r"(a3), "r"(b0), "r"(b1));
}
__device__ __forceinline__ int ldcs_i(const int* p) {
    int v;
    asm volatile("ld.global.cs.s32 %0, [%1];" : "=r"(v) : "l"(p));
    return v;
}

// =====================================================================
// K1: Wx = x @ W (full W staged once, single sync), plus e_src/e_dst
// (pre-scaled by log2e). Dynamic smem 72 KB -> opt-in attribute.
// =====================================================================
__global__ __launch_bounds__(256) void k_gemm(const float* __restrict__ x,
                                              const float* __restrict__ W,
                                              const float* __restrict__ a) {
    extern __shared__ __align__(16) float sm[];
    float* Ws = sm;            // 128*128 floats = 64 KB
    float* xs = sm + 16384;    // 16*128  floats =  8 KB
    const int t = threadIdx.x;
    const int rowbase = blockIdx.x * 16;

    #pragma unroll
    for (int p = 0; p < 16; p++) {
        int idx = t + 256 * p;
        int kr = idx >> 5, c4 = (idx & 31) << 2;
        *(float4*)&Ws[kr * 128 + c4] = *(const float4*)&W[(size_t)kr * NC + c4];
    }
    #pragma unroll
    for (int p = 0; p < 2; p++) {
        int idx = t + 256 * p;
        int r = idx >> 5, c4 = (idx & 31) << 2;
        *(float4*)&xs[r * 128 + c4] =
            *(const float4*)&x[(size_t)(rowbase + r) * INF_ + c4];
    }
    __syncthreads();

    const int cg = t & 31;
    const int rg = t >> 5;
    const int c0 = cg << 2;

    float acc[2][4];
    #pragma unroll
    for (int i = 0; i < 2; i++)
        #pragma unroll
        for (int j = 0; j < 4; j++) acc[i][j] = 0.f;

    #pragma unroll 8
    for (int k = 0; k < INF_; k++) {
        float4 w4 = *(const float4*)&Ws[k * 128 + c0];
        #pragma unroll
        for (int rr = 0; rr < 2; rr++) {
            float xv = xs[(rg * 2 + rr) * 128 + k];
            acc[rr][0] += xv * w4.x;
            acc[rr][1] += xv * w4.y;
            acc[rr][2] += xv * w4.z;
            acc[rr][3] += xv * w4.w;
        }
    }

    const int h = cg >> 3;
    const int fbase = c0 & 31;
    #pragma unroll
    for (int rr = 0; rr < 2; rr++) {
        int row = rowbase + rg * 2 + rr;
        *(float4*)&g_Wx[(size_t)row * NC + c0] =
            make_float4(acc[rr][0], acc[rr][1], acc[rr][2], acc[rr][3]);
        float es = 0.f, ed = 0.f;
        #pragma unroll
        for (int q = 0; q < 4; q++) {
            float av = __ldg(&a[h * (2 * OUTF) + fbase + q]);
            float bv = __ldg(&a[h * (2 * OUTF) + OUTF + fbase + q]);
            es += acc[rr][q] * av;
            ed += acc[rr][q] * bv;
        }
        es += __shfl_xor_sync(0xffffffffu, es, 1);
        es += __shfl_xor_sync(0xffffffffu, es, 2);
        es += __shfl_xor_sync(0xffffffffu, es, 4);
        ed += __shfl_xor_sync(0xffffffffu, ed, 1);
        ed += __shfl_xor_sync(0xffffffffu, ed, 2);
        ed += __shfl_xor_sync(0xffffffffu, ed, 4);
        if ((cg & 7) == 0) {
            g_es[row * NH + h] = es * LOG2E;   // log2 domain (leaky is scale-inv)
            g_ed[row * NH + h] = ed * LOG2E;
        }
    }
}

// =====================================================================
// K2: HMMA tf32 attention aggregation, small per-warp tile.
// Grid (JSPLIT, NN/ITILE) = (8, 64). Block 256 = 8 warps.
// Warp w: head h = w&3, i-half = w>>2 -> 32i x 32f output over K=512
// (2 m-tiles x 4 n-tiles of m16n8k8, acc = 32 regs -> no spills,
// 6 warps/SMSP at 3 blocks/SM for latency cover).
// Pipeline kept: adj for round r+1 prefetched into regs at round top,
// ballot-packed + Wx^T restaged after the MMA loop; 1 barrier/round.
// =====================================================================
__global__ __launch_bounds__(256, 3) void k_attn(const int* __restrict__ adj) {
    __shared__ __align__(16) uint32_t WxS[2][JSTEP * WXS_STRIDE];  // 34816 B
    __shared__ __align__(16) float edS[JCHUNK * NH];               //  8192 B
    __shared__ uint32_t adjW[2][ITILE];                            //   512 B

    const int t = threadIdx.x;
    const int w = t >> 5, lane = t & 31;
    const int g = lane >> 2, tig = lane & 3;
    const int h = w & 3;                 // head
    const int ihalf = w >> 2;            // i-half of the 64-row tile
    const int ibase = blockIdx.y * ITILE;
    const int jc = blockIdx.x;
    const int jbase = jc * JCHUNK;
    const int gib = ibase + ihalf * 32;  // this warp's first i-row

    // stage ed chunk once (512 x 4 floats, 2 float4 per thread)
    for (int idx = t; idx < JCHUNK; idx += 256)
        *(float4*)&edS[idx * 4] = *(const float4*)&g_ed[(size_t)(jbase + idx) * NH];

    // es for my 4 rows (log2 domain)
    float es_[2][2];
    #pragma unroll
    for (int mt = 0; mt < 2; mt++) {
        es_[mt][0] = g_es[(size_t)(gib + mt * 16 + g) * NH + h];
        es_[mt][1] = g_es[(size_t)(gib + mt * 16 + g + 8) * NH + h];
    }

    float acc[2][4][4];
    #pragma unroll
    for (int mt = 0; mt < 2; mt++)
        #pragma unroll
        for (int nt = 0; nt < 4; nt++)
            #pragma unroll
            for (int q = 0; q < 4; q++) acc[mt][nt][q] = 0.f;
    float z[2][2];
    #pragma unroll
    for (int mt = 0; mt < 2; mt++) { z[mt][0] = 0.f; z[mt][1] = 0.f; }

    // adj staging rows for this warp: ibase + w*8 .. +7 (lane = j)
    const int* arow = adj + (size_t)(ibase + w * 8) * NN + jbase;

    // ---------------- prologue: stage round 0 ----------------
    {
        int av[8];
        #pragma unroll
        for (int q = 0; q < 8; q++) av[q] = ldcs_i(&arow[(size_t)q * NN + lane]);
        #pragma unroll
        for (int q = 0; q < 8; q++) {
            uint32_t m = __ballot_sync(0xffffffffu, av[q] != 0);
            if (lane == 0) adjW[0][w * 8 + q] = m;
        }
        #pragma unroll
        for (int p = 0; p < 4; p++) {
            int idx = t + 256 * p;
            int j = idx >> 5, c4 = (idx & 31) << 2;
            float4 v = *(const float4*)&g_Wx[(size_t)(jbase + j) * NC + c4];
            uint32_t* d = &WxS[0][j * WXS_STRIDE + c4];
            d[0] = cvt_tf32(v.x); d[1] = cvt_tf32(v.y);
            d[2] = cvt_tf32(v.z); d[3] = cvt_tf32(v.w);
        }
    }
    __syncthreads();

    // ---------------- main loop ----------------
    for (int r = 0; r < NROUND; r++) {
        const int b = r & 1;

        // EARLY: prefetch next round's adj (consumed after the MMA loop)
        int avn[8];
        if (r < NROUND - 1) {
            #pragma unroll
            for (int q = 0; q < 8; q++)
                avn[q] = ldcs_i(&arow[(size_t)q * NN + (r + 1) * JSTEP + lane]);
        }

        // my 4 mask words for this round
        uint32_t aw[2][2];
        #pragma unroll
        for (int mt = 0; mt < 2; mt++) {
            aw[mt][0] = adjW[b][ihalf * 32 + mt * 16 + g];
            aw[mt][1] = adjW[b][ihalf * 32 + mt * 16 + g + 8];
        }

        #pragma unroll
        for (int ks = 0; ks < 4; ks++) {
            // B fragments (4 n-tiles), conflict-free (banks 8*tig+g)
            uint32_t b0[4], b1[4];
            #pragma unroll
            for (int nt = 0; nt < 4; nt++) {
                b0[nt] = WxS[b][(ks * 8 + tig) * WXS_STRIDE + h * OUTF + nt * 8 + g];
                b1[nt] = WxS[b][(ks * 8 + tig + 4) * WXS_STRIDE + h * OUTF + nt * 8 + g];
            }
            float ed0 = edS[(r * JSTEP + ks * 8 + tig) * NH + h];
            float ed1 = edS[(r * JSTEP + ks * 8 + tig + 4) * NH + h];
            const int j0 = ks * 8 + tig, j1 = j0 + 4;

            #pragma unroll
            for (int mt = 0; mt < 2; mt++) {
                float p0 = pval(es_[mt][0] + ed0, (aw[mt][0] >> j0) & 1u);
                float p1 = pval(es_[mt][1] + ed0, (aw[mt][1] >> j0) & 1u);
                float p2 = pval(es_[mt][0] + ed1, (aw[mt][0] >> j1) & 1u);
                float p3 = pval(es_[mt][1] + ed1, (aw[mt][1] >> j1) & 1u);
                uint32_t a0 = cvt_tf32(p0), a1 = cvt_tf32(p1);
                uint32_t a2 = cvt_tf32(p2), a3 = cvt_tf32(p3);
                z[mt][0] += __uint_as_float(a0) + __uint_as_float(a2);
                z[mt][1] += __uint_as_float(a1) + __uint_as_float(a3);
                #pragma unroll
                for (int nt = 0; nt < 4; nt++)
                    mma8(acc[mt][nt], a0, a1, a2, a3, b0[nt], b1[nt]);
            }
        }

        // LATE: pack prefetched adj + restage Wx^T into buffer b^1
        if (r < NROUND - 1) {
            #pragma unroll
            for (int q = 0; q < 8; q++) {
                uint32_t m = __ballot_sync(0xffffffffu, avn[q] != 0);
                if (lane == 0) adjW[b ^ 1][w * 8 + q] = m;
            }
            #pragma unroll
            for (int p = 0; p < 4; p++) {
                int idx = t + 256 * p;
                int j = idx >> 5, c4 = (idx & 31) << 2;
                float4 v = *(const float4*)
                    &g_Wx[(size_t)(jbase + (r + 1) * JSTEP + j) * NC + c4];
                uint32_t* d = &WxS[b ^ 1][j * WXS_STRIDE + c4];
                d[0] = cvt_tf32(v.x); d[1] = cvt_tf32(v.y);
                d[2] = cvt_tf32(v.z); d[3] = cvt_tf32(v.w);
            }
        }
        __syncthreads();
    }

    // ---- epilogue: D fragments -> partial numerators; Z reduce ----
    float* np = g_nump[jc];
    #pragma unroll
    for (int mt = 0; mt < 2; mt++) {
        int r0 = gib + mt * 16 + g;
        #pragma unroll
        for (int nt = 0; nt < 4; nt++) {
            int c = h * OUTF + nt * 8 + tig * 2;
            *(float2*)&np[(size_t)r0 * NC + c] =
                make_float2(acc[mt][nt][0], acc[mt][nt][1]);
            *(float2*)&np[(size_t)(r0 + 8) * NC + c] =
                make_float2(acc[mt][nt][2], acc[mt][nt][3]);
        }
        float z0 = z[mt][0], z1 = z[mt][1];
        z0 += __shfl_xor_sync(0xffffffffu, z0, 1);
        z0 += __shfl_xor_sync(0xffffffffu, z0, 2);
        z1 += __shfl_xor_sync(0xffffffffu, z1, 1);
        z1 += __shfl_xor_sync(0xffffffffu, z1, 2);
        if (tig == 0) {
            g_Zp[jc][(size_t)r0 * NH + h] = z0;
            g_Zp[jc][(size_t)(r0 + 8) * NH + h] = z1;
        }
    }
}

// =====================================================================
// K3: normalize — out = (sum_s num_s) / (sum_s Z_s).
// =====================================================================
__global__ __launch_bounds__(256) void k_norm(float* __restrict__ out) {
    int g = blockIdx.x * 256 + threadIdx.x;
    int i = g >> 5;
    int c4 = (g & 31) << 2;
    int h = c4 >> 5;
    float4 num = make_float4(0.f, 0.f, 0.f, 0.f);
    float Z = 0.f;
    #pragma unroll
    for (int s = 0; s < JSPLIT; s++) {
        float4 v = *(const float4*)&g_nump[s][(size_t)i * NC + c4];
        num.x += v.x; num.y += v.y; num.z += v.z; num.w += v.w;
        Z += g_Zp[s][i * NH + h];
    }
    float inv = 1.f / Z;
    *(float4*)&out[(size_t)i * NC + c4] =
        make_float4(num.x * inv, num.y * inv, num.z * inv, num.w * inv);
}

// =====================================================================
extern "C" void kernel_launch(void* const* d_in, const int* in_sizes, int n_in,
                              void* d_out, int out_size) {
    const float* x = nullptr;
    const int*   adj = nullptr;
    const float* W = nullptr;
    const float* a = nullptr;
    for (int i = 0; i < n_in; i++) {
        switch (in_sizes[i]) {
            case NN * INF_:       x   = (const float*)d_in[i]; break;
            case NN * NN:         adj = (const int*)d_in[i];   break;
            case INF_ * NC:       W   = (const float*)d_in[i]; break;
            case NH * 2 * OUTF:   a   = (const float*)d_in[i]; break;
            default: break;
        }
    }
    float* out = (float*)d_out;

    // k_gemm uses 72 KB dynamic smem: opt-in (host attribute; graph-safe).
    const int gemm_smem = (16384 + 2048) * (int)sizeof(float);  // 73728
    cudaFuncSetAttribute(k_gemm, cudaFuncAttributeMaxDynamicSharedMemorySize,
                         gemm_smem);

    k_gemm<<<NN / 16, 256, gemm_smem>>>(x, W, a);
    dim3 g_attn(JSPLIT, NN / ITILE);   // (8, 64)
    k_attn<<<g_attn, 256>>>(adj);
    k_norm<<<(NN * NC / 4) / 256, 256>>>(out);
    (void)out_size;
}

// round 11
// speedup vs baseline: 1.0779x; 1.0779x over previous
#include <cuda_runtime.h>
#include <cstdint>

// Problem constants (fixed by the reference)
#define NN    4096     // nodes
#define INF_  128      // input features
#define OUTF  32       // output features per head
#define NH    4        // heads
#define NC    128      // NH*OUTF

// Attention tiling
#define ITILE  64                 // i-rows per block
#define JSPLIT 8                  // j-range splits (additive partial softmax)
#define JCHUNK (NN / JSPLIT)      // 512
#define JSTEP  32                 // j's per round
#define NROUND (JCHUNK / JSTEP)   // 16

#define LOG2E 1.4426950408889634f
#define WXS_STRIDE 136            // 128 + 8 pad: B-frag reads bank-conflict-free

// ---------------- scratch (device globals; no allocation allowed) ----------------
__device__ __align__(16) float g_Wx[NN * NC];            // 2 MB
__device__ __align__(16) float g_es[NN * NH];            // e_src * log2e
__device__ __align__(16) float g_ed[NN * NH];            // e_dst * log2e
__device__ __align__(16) float g_nump[JSPLIT][NN * NC];  // 16 MB partial numerators
__device__ __align__(16) float g_Zp[JSPLIT][NN * NH];    // partial denominators

// ---------------- helpers ----------------
__device__ __forceinline__ uint32_t cvt_tf32(float v) {
    uint32_t r;
    asm("cvt.rna.tf32.f32 %0, %1;" : "=r"(r) : "f"(v));
    return r;
}
// P = mask * 2^(leaky(s)); s already in log2 domain
__device__ __forceinline__ float pval(float s, uint32_t bit) {
    float lk = fmaxf(s, 0.2f * s);
    float e;
    asm("ex2.approx.f32 %0, %1;" : "=f"(e) : "f"(lk));
    return bit ? e : 0.0f;
}
// m16n8k8 tf32 HMMA (sm_80+ baseline PTX; works on plain sm_100)
__device__ __forceinline__ void mma8(float* d, uint32_t a0, uint32_t a1,
                                     uint32_t a2, uint32_t a3,
                                     uint32_t b0, uint32_t b1) {
    asm volatile(
        "mma.sync.aligned.m16n8k8.row.col.f32.tf32.tf32.f32 "
        "{%0,%1,%2,%3}, {%4,%5,%6,%7}, {%8,%9}, {%0,%1,%2,%3};"
        : "+f"(d[0]), "+f"(d[1]), "+f"(d[2]), "+f"(d[3])
        : "r"(a0), "r"(a1), "r"(a2), "r"(a3), "r"(b0), "r"(b1));
}
__device__ __forceinline__ int ldcs_i(const int* p) {
    int v;
    asm volatile("ld.global.cs.s32 %0, [%1];" : "=r"(v) : "l"(p));
    return v;
}

// =====================================================================
// K1: Wx = x @ W, plus e_src/e_dst (pre-scaled by log2e).
// 512 threads/block, warp = one row (16 rows/block), 4 outputs/thread.
// W staged in two 64-row chunks (32 KB); 40 KB static smem, grid 256,
// ~2x the warps/SM of the previous version.
// =====================================================================
__global__ __launch_bounds__(512) void k_gemm(const float* __restrict__ x,
                                              const float* __restrict__ W,
                                              const float* __restrict__ a) {
    __shared__ __align__(16) float Ws[64 * 128];   // 32 KB (k-chunk of W)
    __shared__ __align__(16) float xs[16 * 128];   //  8 KB (x row tile)
    const int t = threadIdx.x;
    const int rowbase = blockIdx.x * 16;
    const int rg = t >> 5;        // warp = row (0..15)
    const int cg = t & 31;        // lane = col group
    const int c0 = cg << 2;

    // load x tile (16 rows = 512 float4, 1 per thread)
    {
        int r = t >> 5, c4 = (t & 31) << 2;
        *(float4*)&xs[r * 128 + c4] =
            *(const float4*)&x[(size_t)(rowbase + r) * INF_ + c4];
    }

    float acc[4] = {0.f, 0.f, 0.f, 0.f};

    for (int kc = 0; kc < INF_; kc += 64) {
        __syncthreads();
        #pragma unroll
        for (int p = 0; p < 4; p++) {
            int idx = t + 512 * p;               // 0..2047 float4's
            int kr = idx >> 5, c4 = (idx & 31) << 2;
            *(float4*)&Ws[kr * 128 + c4] =
                *(const float4*)&W[(size_t)(kc + kr) * NC + c4];
        }
        __syncthreads();
        #pragma unroll 8
        for (int k = 0; k < 64; k++) {
            float4 w4 = *(const float4*)&Ws[k * 128 + c0];
            float xv = xs[rg * 128 + kc + k];    // broadcast within warp
            acc[0] += xv * w4.x;
            acc[1] += xv * w4.y;
            acc[2] += xv * w4.z;
            acc[3] += xv * w4.w;
        }
    }

    const int h = cg >> 3;
    const int fbase = c0 & 31;
    const int row = rowbase + rg;
    *(float4*)&g_Wx[(size_t)row * NC + c0] =
        make_float4(acc[0], acc[1], acc[2], acc[3]);
    float es = 0.f, ed = 0.f;
    #pragma unroll
    for (int q = 0; q < 4; q++) {
        float av = __ldg(&a[h * (2 * OUTF) + fbase + q]);
        float bv = __ldg(&a[h * (2 * OUTF) + OUTF + fbase + q]);
        es += acc[q] * av;
        ed += acc[q] * bv;
    }
    es += __shfl_xor_sync(0xffffffffu, es, 1);
    es += __shfl_xor_sync(0xffffffffu, es, 2);
    es += __shfl_xor_sync(0xffffffffu, es, 4);
    ed += __shfl_xor_sync(0xffffffffu, ed, 1);
    ed += __shfl_xor_sync(0xffffffffu, ed, 2);
    ed += __shfl_xor_sync(0xffffffffu, ed, 4);
    if ((cg & 7) == 0) {
        g_es[row * NH + h] = es * LOG2E;   // log2 domain (leaky is scale-inv)
        g_ed[row * NH + h] = ed * LOG2E;
    }
}

// =====================================================================
// K2: HMMA tf32 attention aggregation, software-pipelined (R9 structure).
// Grid (JSPLIT, NN/ITILE) = (8, 64). Block 128 = 4 warps; warp == head.
// Each warp: 64i x 32f output over K=512, as 4x4 m16n8k8 tiles x 4 ks.
// launch_bounds (128, 3): 170-reg cap -> no spills, full scheduling
// freedom for the FADD->FMAX->MUFU->SEL->CVT->HMMA chains.
// =====================================================================
__global__ __launch_bounds__(128, 3) void k_attn(const int* __restrict__ adj) {
    __shared__ __align__(16) uint32_t WxS[2][JSTEP * WXS_STRIDE];  // 34816 B
    __shared__ __align__(16) float edS[JCHUNK * NH];               //  8192 B
    __shared__ uint32_t adjW[2][ITILE];                            //   512 B

    const int t = threadIdx.x;
    const int w = t >> 5, lane = t & 31;
    const int g = lane >> 2, tig = lane & 3;
    const int h = w;                    // warp == head
    const int ibase = blockIdx.y * ITILE;
    const int jc = blockIdx.x;
    const int jbase = jc * JCHUNK;

    // stage ed chunk once (512 x 4 floats, 4 float4 per thread)
    for (int idx = t; idx < JCHUNK; idx += 128)
        *(float4*)&edS[idx * 4] = *(const float4*)&g_ed[(size_t)(jbase + idx) * NH];

    // es for my 8 rows (log2 domain)
    float es_[4][2];
    #pragma unroll
    for (int mt = 0; mt < 4; mt++) {
        es_[mt][0] = g_es[(size_t)(ibase + mt * 16 + g) * NH + h];
        es_[mt][1] = g_es[(size_t)(ibase + mt * 16 + g + 8) * NH + h];
    }

    float acc[4][4][4];
    #pragma unroll
    for (int mt = 0; mt < 4; mt++)
        #pragma unroll
        for (int nt = 0; nt < 4; nt++)
            #pragma unroll
            for (int q = 0; q < 4; q++) acc[mt][nt][q] = 0.f;
    float z[4][2];
    #pragma unroll
    for (int mt = 0; mt < 4; mt++) { z[mt][0] = 0.f; z[mt][1] = 0.f; }

    // adj staging rows for this warp: ibase + w*16 .. +15 (lane = j)
    const int* arow = adj + (size_t)(ibase + w * 16) * NN + jbase;

    // ---------------- prologue: stage round 0 ----------------
    {
        int av[16];
        #pragma unroll
        for (int q = 0; q < 16; q++) av[q] = ldcs_i(&arow[(size_t)q * NN + lane]);
        #pragma unroll
        for (int q = 0; q < 16; q++) {
            uint32_t m = __ballot_sync(0xffffffffu, av[q] != 0);
            if (lane == 0) adjW[0][w * 16 + q] = m;
        }
        #pragma unroll
        for (int p = 0; p < 8; p++) {
            int idx = t + 128 * p;
            int j = idx >> 5, c4 = (idx & 31) << 2;
            float4 v = *(const float4*)&g_Wx[(size_t)(jbase + j) * NC + c4];
            uint32_t* d = &WxS[0][j * WXS_STRIDE + c4];
            d[0] = cvt_tf32(v.x); d[1] = cvt_tf32(v.y);
            d[2] = cvt_tf32(v.z); d[3] = cvt_tf32(v.w);
        }
    }
    __syncthreads();

    // ---------------- main loop ----------------
    for (int r = 0; r < NROUND; r++) {
        const int b = r & 1;

        // EARLY: prefetch next round's adj (consumed after the MMA loop)
        int avn[16];
        if (r < NROUND - 1) {
            #pragma unroll
            for (int q = 0; q < 16; q++)
                avn[q] = ldcs_i(&arow[(size_t)q * NN + (r + 1) * JSTEP + lane]);
        }

        // my 8 mask words for this round
        uint32_t aw[4][2];
        #pragma unroll
        for (int mt = 0; mt < 4; mt++) {
            aw[mt][0] = adjW[b][mt * 16 + g];
            aw[mt][1] = adjW[b][mt * 16 + g + 8];
        }

        #pragma unroll
        for (int ks = 0; ks < 4; ks++) {
            // B fragments (4 n-tiles), conflict-free (banks 8*tig+g)
            uint32_t b0[4], b1[4];
            #pragma unroll
            for (int nt = 0; nt < 4; nt++) {
                b0[nt] = WxS[b][(ks * 8 + tig) * WXS_STRIDE + h * OUTF + nt * 8 + g];
                b1[nt] = WxS[b][(ks * 8 + tig + 4) * WXS_STRIDE + h * OUTF + nt * 8 + g];
            }
            float ed0 = edS[(r * JSTEP + ks * 8 + tig) * NH + h];
            float ed1 = edS[(r * JSTEP + ks * 8 + tig + 4) * NH + h];
            const int j0 = ks * 8 + tig, j1 = j0 + 4;

            #pragma unroll
            for (int mt = 0; mt < 4; mt++) {
                float p0 = pval(es_[mt][0] + ed0, (aw[mt][0] >> j0) & 1u);
                float p1 = pval(es_[mt][1] + ed0, (aw[mt][1] >> j0) & 1u);
                float p2 = pval(es_[mt][0] + ed1, (aw[mt][0] >> j1) & 1u);
                float p3 = pval(es_[mt][1] + ed1, (aw[mt][1] >> j1) & 1u);
                uint32_t a0 = cvt_tf32(p0), a1 = cvt_tf32(p1);
                uint32_t a2 = cvt_tf32(p2), a3 = cvt_tf32(p3);
                z[mt][0] += __uint_as_float(a0) + __uint_as_float(a2);
                z[mt][1] += __uint_as_float(a1) + __uint_as_float(a3);
                #pragma unroll
                for (int nt = 0; nt < 4; nt++)
                    mma8(acc[mt][nt], a0, a1, a2, a3, b0[nt], b1[nt]);
            }
        }

        // LATE: pack prefetched adj + restage Wx^T into buffer b^1
        if (r < NROUND - 1) {
            #pragma unroll
            for (int q = 0; q < 16; q++) {
                uint32_t m = __ballot_sync(0xffffffffu, avn[q] != 0);
                if (lane == 0) adjW[b ^ 1][w * 16 + q] = m;
            }
            #pragma unroll
            for (int p = 0; p < 8; p++) {
                int idx = t + 128 * p;
                int j = idx >> 5, c4 = (idx & 31) << 2;
                float4 v = *(const float4*)
                    &g_Wx[(size_t)(jbase + (r + 1) * JSTEP + j) * NC + c4];
                uint32_t* d = &WxS[b ^ 1][j * WXS_STRIDE + c4];
                d[0] = cvt_tf32(v.x); d[1] = cvt_tf32(v.y);
                d[2] = cvt_tf32(v.z); d[3] = cvt_tf32(v.w);
            }
        }
        __syncthreads();
    }

    // ---- epilogue: D fragments -> partial numerators; Z reduce ----
    float* np = g_nump[jc];
    #pragma unroll
    for (int mt = 0; mt < 4; mt++) {
        int r0 = ibase + mt * 16 + g;
        #pragma unroll
        for (int nt = 0; nt < 4; nt++) {
            int c = h * OUTF + nt * 8 + tig * 2;
            *(float2*)&np[(size_t)r0 * NC + c] =
                make_float2(acc[mt][nt][0], acc[mt][nt][1]);
            *(float2*)&np[(size_t)(r0 + 8) * NC + c] =
                make_float2(acc[mt][nt][2], acc[mt][nt][3]);
        }
        float z0 = z[mt][0], z1 = z[mt][1];
        z0 += __shfl_xor_sync(0xffffffffu, z0, 1);
        z0 += __shfl_xor_sync(0xffffffffu, z0, 2);
        z1 += __shfl_xor_sync(0xffffffffu, z1, 1);
        z1 += __shfl_xor_sync(0xffffffffu, z1, 2);
        if (tig == 0) {
            g_Zp[jc][(size_t)r0 * NH + h] = z0;
            g_Zp[jc][(size_t)(r0 + 8) * NH + h] = z1;
        }
    }
}

// =====================================================================
// K3: normalize — out = (sum_s num_s) / (sum_s Z_s).
// =====================================================================
__global__ __launch_bounds__(256) void k_norm(float* __restrict__ out) {
    int g = blockIdx.x * 256 + threadIdx.x;
    int i = g >> 5;
    int c4 = (g & 31) << 2;
    int h = c4 >> 5;
    float4 num = make_float4(0.f, 0.f, 0.f, 0.f);
    float Z = 0.f;
    #pragma unroll
    for (int s = 0; s < JSPLIT; s++) {
        float4 v = *(const float4*)&g_nump[s][(size_t)i * NC + c4];
        num.x += v.x; num.y += v.y; num.z += v.z; num.w += v.w;
        Z += g_Zp[s][i * NH + h];
    }
    float inv = 1.f / Z;
    *(float4*)&out[(size_t)i * NC + c4] =
        make_float4(num.x * inv, num.y * inv, num.z * inv, num.w * inv);
}

// =====================================================================
extern "C" void kernel_launch(void* const* d_in, const int* in_sizes, int n_in,
                              void* d_out, int out_size) {
    const float* x = nullptr;
    const int*   adj = nullptr;
    const float* W = nullptr;
    const float* a = nullptr;
    for (int i = 0; i < n_in; i++) {
        switch (in_sizes[i]) {
            case NN * INF_:       x   = (const float*)d_in[i]; break;
            case NN * NN:         adj = (const int*)d_in[i];   break;
            case INF_ * NC:       W   = (const float*)d_in[i]; break;
            case NH * 2 * OUTF:   a   = (const float*)d_in[i]; break;
            default: break;
        }
    }
    float* out = (float*)d_out;

    k_gemm<<<NN / 16, 512>>>(x, W, a);
    dim3 g_attn(JSPLIT, NN / ITILE);   // (8, 64)
    k_attn<<<g_attn, 128>>>(adj);
    k_norm<<<(NN * NC / 4) / 256, 256>>>(out);
    (void)out_size;
}

// round 12
// speedup vs baseline: 1.4727x; 1.3662x over previous
#include <cuda_runtime.h>
#include <cstdint>

// Problem constants (fixed by the reference)
#define NN    4096     // nodes
#define INF_  128      // input features
#define OUTF  32       // output features per head
#define NH    4        // heads
#define NC    128      // NH*OUTF

// Attention tiling
#define ITILE  64                 // i-rows per block
#define JSPLIT 8                  // j-range splits (additive partial softmax)
#define JCHUNK (NN / JSPLIT)      // 512
#define JSTEP  32                 // j's per round
#define NROUND (JCHUNK / JSTEP)   // 16

#define LOG2E 1.4426950408889634f
#define WXS_STRIDE 136            // 128 + 8 pad (uint32 units)

// ---------------- scratch (device globals; no allocation allowed) ----------------
__device__ __align__(16) float g_Wx[NN * NC];            // 2 MB
__device__ __align__(16) float g_es[NN * NH];            // e_src * log2e
__device__ __align__(16) float g_ed[NN * NH];            // e_dst * log2e
__device__ __align__(16) float g_nump[JSPLIT][NN * NC];  // 16 MB partial numerators
__device__ __align__(16) float g_Zp[JSPLIT][NN * NH];    // partial denominators

// ---------------- helpers ----------------
// pack two f32 -> bf16x2 (lo = first k element, hi = second)
__device__ __forceinline__ uint32_t pack_bf16(float lo, float hi) {
    uint32_t r;
    asm("cvt.rn.bf16x2.f32 %0, %1, %2;" : "=r"(r) : "f"(hi), "f"(lo));
    return r;
}
// P = mask * 2^(leaky(s)); s already in log2 domain
__device__ __forceinline__ float pval(float s, uint32_t bit) {
    float lk = fmaxf(s, 0.2f * s);
    float e;
    asm("ex2.approx.f32 %0, %1;" : "=f"(e) : "f"(lk));
    return bit ? e : 0.0f;
}
// m16n8k16 bf16 HMMA (sm_80+ baseline PTX)
__device__ __forceinline__ void mma16(float* d, uint32_t a0, uint32_t a1,
                                      uint32_t a2, uint32_t a3,
                                      uint32_t b0, uint32_t b1) {
    asm volatile(
        "mma.sync.aligned.m16n8k16.row.col.f32.bf16.bf16.f32 "
        "{%0,%1,%2,%3}, {%4,%5,%6,%7}, {%8,%9}, {%0,%1,%2,%3};"
        : "+f"(d[0]), "+f"(d[1]), "+f"(d[2]), "+f"(d[3])
        : "r"(a0), "r"(a1), "r"(a2), "r"(a3), "r"(b0), "r"(b1));
}
__device__ __forceinline__ int ldcs_i(const int* p) {
    int v;
    asm volatile("ld.global.cs.s32 %0, [%1];" : "=r"(v) : "l"(p));
    return v;
}

// =====================================================================
// K1: Wx = x @ W (full W staged once, single sync), plus e_src/e_dst
// (pre-scaled by log2e). Dynamic smem 72 KB -> opt-in attribute.
// (R9 version: measured 12.2us.)
// =====================================================================
__global__ __launch_bounds__(256) void k_gemm(const float* __restrict__ x,
                                              const float* __restrict__ W,
                                              const float* __restrict__ a) {
    extern __shared__ __align__(16) float sm[];
    float* Ws = sm;            // 128*128 floats = 64 KB
    float* xs = sm + 16384;    // 16*128  floats =  8 KB
    const int t = threadIdx.x;
    const int rowbase = blockIdx.x * 16;

    #pragma unroll
    for (int p = 0; p < 16; p++) {
        int idx = t + 256 * p;
        int kr = idx >> 5, c4 = (idx & 31) << 2;
        *(float4*)&Ws[kr * 128 + c4] = *(const float4*)&W[(size_t)kr * NC + c4];
    }
    #pragma unroll
    for (int p = 0; p < 2; p++) {
        int idx = t + 256 * p;
        int r = idx >> 5, c4 = (idx & 31) << 2;
        *(float4*)&xs[r * 128 + c4] =
            *(const float4*)&x[(size_t)(rowbase + r) * INF_ + c4];
    }
    __syncthreads();

    const int cg = t & 31;
    const int rg = t >> 5;
    const int c0 = cg << 2;

    float acc[2][4];
    #pragma unroll
    for (int i = 0; i < 2; i++)
        #pragma unroll
        for (int j = 0; j < 4; j++) acc[i][j] = 0.f;

    #pragma unroll 8
    for (int k = 0; k < INF_; k++) {
        float4 w4 = *(const float4*)&Ws[k * 128 + c0];
        #pragma unroll
        for (int rr = 0; rr < 2; rr++) {
            float xv = xs[(rg * 2 + rr) * 128 + k];
            acc[rr][0] += xv * w4.x;
            acc[rr][1] += xv * w4.y;
            acc[rr][2] += xv * w4.z;
            acc[rr][3] += xv * w4.w;
        }
    }

    const int h = cg >> 3;
    const int fbase = c0 & 31;
    #pragma unroll
    for (int rr = 0; rr < 2; rr++) {
        int row = rowbase + rg * 2 + rr;
        *(float4*)&g_Wx[(size_t)row * NC + c0] =
            make_float4(acc[rr][0], acc[rr][1], acc[rr][2], acc[rr][3]);
        float es = 0.f, ed = 0.f;
        #pragma unroll
        for (int q = 0; q < 4; q++) {
            float av = __ldg(&a[h * (2 * OUTF) + fbase + q]);
            float bv = __ldg(&a[h * (2 * OUTF) + OUTF + fbase + q]);
            es += acc[rr][q] * av;
            ed += acc[rr][q] * bv;
        }
        es += __shfl_xor_sync(0xffffffffu, es, 1);
        es += __shfl_xor_sync(0xffffffffu, es, 2);
        es += __shfl_xor_sync(0xffffffffu, es, 4);
        ed += __shfl_xor_sync(0xffffffffu, ed, 1);
        ed += __shfl_xor_sync(0xffffffffu, ed, 2);
        ed += __shfl_xor_sync(0xffffffffu, ed, 4);
        if ((cg & 7) == 0) {
            g_es[row * NH + h] = es * LOG2E;   // log2 domain (leaky is scale-inv)
            g_ed[row * NH + h] = ed * LOG2E;
        }
    }
}

// =====================================================================
// K2: bf16 m16n8k16 HMMA attention aggregation (half the mma ops of the
// tf32 m16n8k8 version). Grid (8, 64). Block 128 = 4 warps; warp == head.
// Warp: 64i x 32f over K=512, 4 m-tiles x 4 n-tiles, 2 k-steps/round.
// WxS holds bf16x2 j-pairs: WxS[j2][c] = pack(Wx[2j2][c], Wx[2j2+1][c]).
// edS2 is head-major [NH][JCHUNK] so ed j-pairs load as one LDS.64.
// adj pipeline (prefetch into regs, ballot after MMA) kept from R9.
// =====================================================================
__global__ __launch_bounds__(128, 3) void k_attn(const int* __restrict__ adj) {
    __shared__ __align__(16) uint32_t WxS[2][16 * WXS_STRIDE];  // 17408 B
    __shared__ __align__(16) float edS2[NH][JCHUNK];            //  8192 B
    __shared__ uint32_t adjW[2][ITILE];                         //   512 B

    const int t = threadIdx.x;
    const int w = t >> 5, lane = t & 31;
    const int g = lane >> 2, tig = lane & 3;
    const int h = w;                    // warp == head
    const int ibase = blockIdx.y * ITILE;
    const int jc = blockIdx.x;
    const int jbase = jc * JCHUNK;

    // stage ed chunk once, transposed to head-major
    for (int idx = t; idx < JCHUNK; idx += 128) {
        float4 v = *(const float4*)&g_ed[(size_t)(jbase + idx) * NH];
        edS2[0][idx] = v.x; edS2[1][idx] = v.y;
        edS2[2][idx] = v.z; edS2[3][idx] = v.w;
    }

    // es for my 8 rows (log2 domain)
    float es_[4][2];
    #pragma unroll
    for (int mt = 0; mt < 4; mt++) {
        es_[mt][0] = g_es[(size_t)(ibase + mt * 16 + g) * NH + h];
        es_[mt][1] = g_es[(size_t)(ibase + mt * 16 + g + 8) * NH + h];
    }

    float acc[4][4][4];
    #pragma unroll
    for (int mt = 0; mt < 4; mt++)
        #pragma unroll
        for (int nt = 0; nt < 4; nt++)
            #pragma unroll
            for (int q = 0; q < 4; q++) acc[mt][nt][q] = 0.f;
    float z[4][2];
    #pragma unroll
    for (int mt = 0; mt < 4; mt++) { z[mt][0] = 0.f; z[mt][1] = 0.f; }

    // adj staging rows for this warp: ibase + w*16 .. +15 (lane = j)
    const int* arow = adj + (size_t)(ibase + w * 16) * NN + jbase;

    // B staging task: idx -> (j2 = idx>>6, c2 = idx&63); 8 tasks/thread
    // ---------------- prologue: stage round 0 ----------------
    {
        int av[16];
        #pragma unroll
        for (int q = 0; q < 16; q++) av[q] = ldcs_i(&arow[(size_t)q * NN + lane]);
        #pragma unroll
        for (int q = 0; q < 16; q++) {
            uint32_t m = __ballot_sync(0xffffffffu, av[q] != 0);
            if (lane == 0) adjW[0][w * 16 + q] = m;
        }
        #pragma unroll
        for (int p = 0; p < 8; p++) {
            int idx = t + 128 * p;
            int j2 = idx >> 6, c2 = (idx & 63) << 1;
            const float* base = &g_Wx[(size_t)(jbase + 2 * j2) * NC + c2];
            float2 r0 = *(const float2*)base;
            float2 r1 = *(const float2*)(base + NC);
            uint2 pk;
            pk.x = pack_bf16(r0.x, r1.x);
            pk.y = pack_bf16(r0.y, r1.y);
            *(uint2*)&WxS[0][j2 * WXS_STRIDE + c2] = pk;
        }
    }
    __syncthreads();

    // ---------------- main loop ----------------
    for (int r = 0; r < NROUND; r++) {
        const int b = r & 1;

        // EARLY: prefetch next round's adj (consumed after the MMA loop)
        int avn[16];
        if (r < NROUND - 1) {
            #pragma unroll
            for (int q = 0; q < 16; q++)
                avn[q] = ldcs_i(&arow[(size_t)q * NN + (r + 1) * JSTEP + lane]);
        }

        // my 8 mask words for this round
        uint32_t aw[4][2];
        #pragma unroll
        for (int mt = 0; mt < 4; mt++) {
            aw[mt][0] = adjW[b][mt * 16 + g];
            aw[mt][1] = adjW[b][mt * 16 + g + 8];
        }

        #pragma unroll
        for (int ks = 0; ks < 2; ks++) {     // two K=16 steps
            const int jq = ks * 8;           // pair base within round
            // B fragments (4 n-tiles), conflict-free (banks 8*tig+g)
            uint32_t b0[4], b1[4];
            #pragma unroll
            for (int nt = 0; nt < 4; nt++) {
                b0[nt] = WxS[b][(jq + tig) * WXS_STRIDE + h * OUTF + nt * 8 + g];
                b1[nt] = WxS[b][(jq + tig + 4) * WXS_STRIDE + h * OUTF + nt * 8 + g];
            }
            // ed pairs for k = 2tig,2tig+1 and 2tig+8,2tig+9 (LDS.64 broadcast)
            float2 eA = *(const float2*)&edS2[h][r * JSTEP + ks * 16 + 2 * tig];
            float2 eB = *(const float2*)&edS2[h][r * JSTEP + ks * 16 + 2 * tig + 8];
            const int j0 = ks * 16 + 2 * tig;      // bit positions in aw
            const int j1 = j0 + 1, j2b = j0 + 8, j3 = j0 + 9;

            #pragma unroll
            for (int mt = 0; mt < 4; mt++) {
                // row g
                float p00 = pval(es_[mt][0] + eA.x, (aw[mt][0] >> j0) & 1u);
                float p01 = pval(es_[mt][0] + eA.y, (aw[mt][0] >> j1) & 1u);
                float p02 = pval(es_[mt][0] + eB.x, (aw[mt][0] >> j2b) & 1u);
                float p03 = pval(es_[mt][0] + eB.y, (aw[mt][0] >> j3) & 1u);
                // row g+8
                float p10 = pval(es_[mt][1] + eA.x, (aw[mt][1] >> j0) & 1u);
                float p11 = pval(es_[mt][1] + eA.y, (aw[mt][1] >> j1) & 1u);
                float p12 = pval(es_[mt][1] + eB.x, (aw[mt][1] >> j2b) & 1u);
                float p13 = pval(es_[mt][1] + eB.y, (aw[mt][1] >> j3) & 1u);
                uint32_t a0 = pack_bf16(p00, p01);
                uint32_t a1 = pack_bf16(p10, p11);
                uint32_t a2 = pack_bf16(p02, p03);
                uint32_t a3 = pack_bf16(p12, p13);
                z[mt][0] += (p00 + p01) + (p02 + p03);
                z[mt][1] += (p10 + p11) + (p12 + p13);
                #pragma unroll
                for (int nt = 0; nt < 4; nt++)
                    mma16(acc[mt][nt], a0, a1, a2, a3, b0[nt], b1[nt]);
            }
        }

        // LATE: pack prefetched adj + restage Wx pairs into buffer b^1
        if (r < NROUND - 1) {
            #pragma unroll
            for (int q = 0; q < 16; q++) {
                uint32_t m = __ballot_sync(0xffffffffu, avn[q] != 0);
                if (lane == 0) adjW[b ^ 1][w * 16 + q] = m;
            }
            #pragma unroll
            for (int p = 0; p < 8; p++) {
                int idx = t + 128 * p;
                int j2 = idx >> 6, c2 = (idx & 63) << 1;
                const float* base =
                    &g_Wx[(size_t)(jbase + (r + 1) * JSTEP + 2 * j2) * NC + c2];
                float2 r0 = *(const float2*)base;
                float2 r1 = *(const float2*)(base + NC);
                uint2 pk;
                pk.x = pack_bf16(r0.x, r1.x);
                pk.y = pack_bf16(r0.y, r1.y);
                *(uint2*)&WxS[b ^ 1][j2 * WXS_STRIDE + c2] = pk;
            }
        }
        __syncthreads();
    }

    // ---- epilogue: D fragments -> partial numerators; Z reduce ----
    float* np = g_nump[jc];
    #pragma unroll
    for (int mt = 0; mt < 4; mt++) {
        int r0 = ibase + mt * 16 + g;
        #pragma unroll
        for (int nt = 0; nt < 4; nt++) {
            int c = h * OUTF + nt * 8 + tig * 2;
            *(float2*)&np[(size_t)r0 * NC + c] =
                make_float2(acc[mt][nt][0], acc[mt][nt][1]);
            *(float2*)&np[(size_t)(r0 + 8) * NC + c] =
                make_float2(acc[mt][nt][2], acc[mt][nt][3]);
        }
        float z0 = z[mt][0], z1 = z[mt][1];
        z0 += __shfl_xor_sync(0xffffffffu, z0, 1);
        z0 += __shfl_xor_sync(0xffffffffu, z0, 2);
        z1 += __shfl_xor_sync(0xffffffffu, z1, 1);
        z1 += __shfl_xor_sync(0xffffffffu, z1, 2);
        if (tig == 0) {
            g_Zp[jc][(size_t)r0 * NH + h] = z0;
            g_Zp[jc][(size_t)(r0 + 8) * NH + h] = z1;
        }
    }
}

// =====================================================================
// K3: normalize — out = (sum_s num_s) / (sum_s Z_s).
// =====================================================================
__global__ __launch_bounds__(256) void k_norm(float* __restrict__ out) {
    int g = blockIdx.x * 256 + threadIdx.x;
    int i = g >> 5;
    int c4 = (g & 31) << 2;
    int h = c4 >> 5;
    float4 num = make_float4(0.f, 0.f, 0.f, 0.f);
    float Z = 0.f;
    #pragma unroll
    for (int s = 0; s < JSPLIT; s++) {
        float4 v = *(const float4*)&g_nump[s][(size_t)i * NC + c4];
        num.x += v.x; num.y += v.y; num.z += v.z; num.w += v.w;
        Z += g_Zp[s][i * NH + h];
    }
    float inv = 1.f / Z;
    *(float4*)&out[(size_t)i * NC + c4] =
        make_float4(num.x * inv, num.y * inv, num.z * inv, num.w * inv);
}

// =====================================================================
extern "C" void kernel_launch(void* const* d_in, const int* in_sizes, int n_in,
                              void* d_out, int out_size) {
    const float* x = nullptr;
    const int*   adj = nullptr;
    const float* W = nullptr;
    const float* a = nullptr;
    for (int i = 0; i < n_in; i++) {
        switch (in_sizes[i]) {
            case NN * INF_:       x   = (const float*)d_in[i]; break;
            case NN * NN:         adj = (const int*)d_in[i];   break;
            case INF_ * NC:       W   = (const float*)d_in[i]; break;
            case NH * 2 * OUTF:   a   = (const float*)d_in[i]; break;
            default: break;
        }
    }
    float* out = (float*)d_out;

    // k_gemm uses 72 KB dynamic smem: opt-in (host attribute; graph-safe).
    const int gemm_smem = (16384 + 2048) * (int)sizeof(float);  // 73728
    cudaFuncSetAttribute(k_gemm, cudaFuncAttributeMaxDynamicSharedMemorySize,
                         gemm_smem);

    k_gemm<<<NN / 16, 256, gemm_smem>>>(x, W, a);
    dim3 g_attn(JSPLIT, NN / ITILE);   // (8, 64)
    k_attn<<<g_attn, 128>>>(adj);
    k_norm<<<(NN * NC / 4) / 256, 256>>>(out);
    (void)out_size;
}

// round 13
// speedup vs baseline: 1.5524x; 1.0542x over previous
#include <cuda_runtime.h>
#include <cstdint>

// Problem constants (fixed by the reference)
#define NN    4096     // nodes
#define INF_  128      // input features
#define OUTF  32       // output features per head
#define NH    4        // heads
#define NC    128      // NH*OUTF

// Attention tiling
#define ITILE  64                 // i-rows per block
#define JSPLIT 8                  // j-range splits (additive partial softmax)
#define JCHUNK (NN / JSPLIT)      // 512
#define JSTEP  32                 // j's per round
#define NROUND (JCHUNK / JSTEP)   // 16

#define LOG2E 1.4426950408889634f
#define WXS_STRIDE 136            // 128 + 8 pad (uint32 units)

// ---------------- scratch (device globals; no allocation allowed) ----------------
__device__ __align__(16) float g_Wx[NN * NC];            // 2 MB
__device__ __align__(16) float g_esA[NN * NH];           // e^{es}
__device__ __align__(16) float g_esC[NN * NH];           // e^{0.2 es}
__device__ __align__(16) float g_edB[NN * NH];           // e^{ed}
__device__ __align__(16) float g_edD[NN * NH];           // e^{0.2 ed}
__device__ __align__(16) float g_nump[JSPLIT][NN * NC];  // 16 MB partial numerators
__device__ __align__(16) float g_Zp[JSPLIT][NN * NH];    // partial denominators

// ---------------- helpers ----------------
__device__ __forceinline__ float ex2f(float x) {
    float r;
    asm("ex2.approx.f32 %0, %1;" : "=f"(r) : "f"(x));
    return r;
}
// pack two f32 -> bf16x2 (lo = first k element, hi = second)
__device__ __forceinline__ uint32_t pack_bf16(float lo, float hi) {
    uint32_t r;
    asm("cvt.rn.bf16x2.f32 %0, %1, %2;" : "=r"(r) : "f"(hi), "f"(lo));
    return r;
}
// d = (c >= 0) ? a : b   (float condition)
__device__ __forceinline__ float slct_f(float a, float b, float c) {
    float d;
    asm("slct.f32.f32 %0, %1, %2, %3;" : "=f"(d) : "f"(a), "f"(b), "f"(c));
    return d;
}
// d = (c >= 0) ? a : b   (int condition — NaN-safe mask select)
__device__ __forceinline__ float slct_i(float a, float b, int c) {
    float d;
    asm("slct.f32.s32 %0, %1, %2, %3;" : "=f"(d) : "f"(a), "f"(b), "r"(c));
    return d;
}
// masked P: p1 = A*B (s>=0 branch), p2 = C*D (s<0 branch), bit via sign of r
__device__ __forceinline__ float pmask(float A, float B, float C, float D,
                                       uint32_t aw, int sh) {
    float p1 = A * B;
    float p2 = C * D;
    float ps = slct_f(p1, p2, p1 - 1.0f);      // sign(es+ed) == sign(A*B - 1)
    int r = (int)(aw << sh);                    // mask bit -> sign position
    return slct_i(0.0f, ps, r);                 // bit=1 -> ps, bit=0 -> 0
}
// bf16x2 halves as floats (for consistent Z accumulation)
__device__ __forceinline__ float bflo(uint32_t pk) {
    return __uint_as_float(pk << 16);
}
__device__ __forceinline__ float bfhi(uint32_t pk) {
    return __uint_as_float(pk & 0xFFFF0000u);
}
// m16n8k16 bf16 HMMA (sm_80+ baseline PTX)
__device__ __forceinline__ void mma16(float* d, uint32_t a0, uint32_t a1,
                                      uint32_t a2, uint32_t a3,
                                      uint32_t b0, uint32_t b1) {
    asm volatile(
        "mma.sync.aligned.m16n8k16.row.col.f32.bf16.bf16.f32 "
        "{%0,%1,%2,%3}, {%4,%5,%6,%7}, {%8,%9}, {%0,%1,%2,%3};"
        : "+f"(d[0]), "+f"(d[1]), "+f"(d[2]), "+f"(d[3])
        : "r"(a0), "r"(a1), "r"(a2), "r"(a3), "r"(b0), "r"(b1));
}
__device__ __forceinline__ int ldcs_i(const int* p) {
    int v;
    asm volatile("ld.global.cs.s32 %0, [%1];" : "=r"(v) : "l"(p));
    return v;
}

// =====================================================================
// K1: Wx = x @ W. 256 threads, 32 rows/block (grid 128), 4 rows x 4 cols
// per thread (FFMA-dense). Full W staged once (64 KB) + x tile (16 KB):
// 80 KB dynamic smem -> opt-in. Epilogue stores the four per-(node,head)
// exponentials A=e^es, C=e^{0.2es}, B=e^ed, D=e^{0.2ed}.
// =====================================================================
__global__ __launch_bounds__(256) void k_gemm(const float* __restrict__ x,
                                              const float* __restrict__ W,
                                              const float* __restrict__ a) {
    extern __shared__ __align__(16) float sm[];
    float* Ws = sm;            // 128*128 floats = 64 KB
    float* xs = sm + 16384;    // 32*128  floats = 16 KB
    const int t = threadIdx.x;
    const int rowbase = blockIdx.x * 32;

    #pragma unroll
    for (int p = 0; p < 16; p++) {
        int idx = t + 256 * p;
        int kr = idx >> 5, c4 = (idx & 31) << 2;
        *(float4*)&Ws[kr * 128 + c4] = *(const float4*)&W[(size_t)kr * NC + c4];
    }
    #pragma unroll
    for (int p = 0; p < 4; p++) {
        int idx = t + 256 * p;
        int r = idx >> 5, c4 = (idx & 31) << 2;
        *(float4*)&xs[r * 128 + c4] =
            *(const float4*)&x[(size_t)(rowbase + r) * INF_ + c4];
    }
    __syncthreads();

    const int cg = t & 31;
    const int rg = t >> 5;     // 0..7, rows rg*4..rg*4+3
    const int c0 = cg << 2;

    float acc[4][4];
    #pragma unroll
    for (int i = 0; i < 4; i++)
        #pragma unroll
        for (int j = 0; j < 4; j++) acc[i][j] = 0.f;

    #pragma unroll 4
    for (int k = 0; k < INF_; k++) {
        float4 w4 = *(const float4*)&Ws[k * 128 + c0];
        #pragma unroll
        for (int rr = 0; rr < 4; rr++) {
            float xv = xs[(rg * 4 + rr) * 128 + k];
            acc[rr][0] += xv * w4.x;
            acc[rr][1] += xv * w4.y;
            acc[rr][2] += xv * w4.z;
            acc[rr][3] += xv * w4.w;
        }
    }

    const int h = cg >> 3;
    const int fbase = c0 & 31;
    #pragma unroll
    for (int rr = 0; rr < 4; rr++) {
        int row = rowbase + rg * 4 + rr;
        *(float4*)&g_Wx[(size_t)row * NC + c0] =
            make_float4(acc[rr][0], acc[rr][1], acc[rr][2], acc[rr][3]);
        float es = 0.f, ed = 0.f;
        #pragma unroll
        for (int q = 0; q < 4; q++) {
            float av = __ldg(&a[h * (2 * OUTF) + fbase + q]);
            float bv = __ldg(&a[h * (2 * OUTF) + OUTF + fbase + q]);
            es += acc[rr][q] * av;
            ed += acc[rr][q] * bv;
        }
        es += __shfl_xor_sync(0xffffffffu, es, 1);
        es += __shfl_xor_sync(0xffffffffu, es, 2);
        es += __shfl_xor_sync(0xffffffffu, es, 4);
        ed += __shfl_xor_sync(0xffffffffu, ed, 1);
        ed += __shfl_xor_sync(0xffffffffu, ed, 2);
        ed += __shfl_xor_sync(0xffffffffu, ed, 4);
        if ((cg & 7) == 0) {
            g_esA[row * NH + h] = ex2f(es * LOG2E);
            g_esC[row * NH + h] = ex2f(0.2f * es * LOG2E);
            g_edB[row * NH + h] = ex2f(ed * LOG2E);
            g_edD[row * NH + h] = ex2f(0.2f * ed * LOG2E);
        }
    }
}

// =====================================================================
// K2: bf16 m16n8k16 HMMA attention aggregation, exp-factorized P:
//   P = adj ? (s>=0 ? A_i*B_j : C_i*D_j) : 0, sign(s) == sign(A*B - 1).
// No MUFU in the hot loop (all 4-cyc fma/alu ops + slct).
// Grid (8, 64). Block 128 = 4 warps; warp == head.
// Warp: 64i x 32f over K=512, 4 m-tiles x 4 n-tiles, 2 k-steps/round.
// adj pipeline (prefetch into regs, ballot after MMA) kept from R12.
// Z accumulated from the bf16-ROUNDED P (numerator-consistent).
// =====================================================================
__global__ __launch_bounds__(128, 3) void k_attn(const int* __restrict__ adj) {
    __shared__ __align__(16) uint32_t WxS[2][16 * WXS_STRIDE];  // 17408 B
    __shared__ __align__(16) float edB[NH][JCHUNK];             //  8192 B
    __shared__ __align__(16) float edD[NH][JCHUNK];             //  8192 B
    __shared__ uint32_t adjW[2][ITILE];                         //   512 B

    const int t = threadIdx.x;
    const int w = t >> 5, lane = t & 31;
    const int g = lane >> 2, tig = lane & 3;
    const int h = w;                    // warp == head
    const int ibase = blockIdx.y * ITILE;
    const int jc = blockIdx.x;
    const int jbase = jc * JCHUNK;

    // stage ed-side exponentials, transposed to head-major
    for (int idx = t; idx < JCHUNK; idx += 128) {
        float4 b4 = *(const float4*)&g_edB[(size_t)(jbase + idx) * NH];
        edB[0][idx] = b4.x; edB[1][idx] = b4.y;
        edB[2][idx] = b4.z; edB[3][idx] = b4.w;
        float4 d4 = *(const float4*)&g_edD[(size_t)(jbase + idx) * NH];
        edD[0][idx] = d4.x; edD[1][idx] = d4.y;
        edD[2][idx] = d4.z; edD[3][idx] = d4.w;
    }

    // es-side exponentials for my 8 rows
    float eA[4][2], eC[4][2];
    #pragma unroll
    for (int mt = 0; mt < 4; mt++) {
        eA[mt][0] = g_esA[(size_t)(ibase + mt * 16 + g) * NH + h];
        eA[mt][1] = g_esA[(size_t)(ibase + mt * 16 + g + 8) * NH + h];
        eC[mt][0] = g_esC[(size_t)(ibase + mt * 16 + g) * NH + h];
        eC[mt][1] = g_esC[(size_t)(ibase + mt * 16 + g + 8) * NH + h];
    }

    float acc[4][4][4];
    #pragma unroll
    for (int mt = 0; mt < 4; mt++)
        #pragma unroll
        for (int nt = 0; nt < 4; nt++)
            #pragma unroll
            for (int q = 0; q < 4; q++) acc[mt][nt][q] = 0.f;
    float z[4][2];
    #pragma unroll
    for (int mt = 0; mt < 4; mt++) { z[mt][0] = 0.f; z[mt][1] = 0.f; }

    // adj staging rows for this warp: ibase + w*16 .. +15 (lane = j)
    const int* arow = adj + (size_t)(ibase + w * 16) * NN + jbase;

    // ---------------- prologue: stage round 0 ----------------
    {
        int av[16];
        #pragma unroll
        for (int q = 0; q < 16; q++) av[q] = ldcs_i(&arow[(size_t)q * NN + lane]);
        #pragma unroll
        for (int q = 0; q < 16; q++) {
            uint32_t m = __ballot_sync(0xffffffffu, av[q] != 0);
            if (lane == 0) adjW[0][w * 16 + q] = m;
        }
        #pragma unroll
        for (int p = 0; p < 8; p++) {
            int idx = t + 128 * p;
            int j2 = idx >> 6, c2 = (idx & 63) << 1;
            const float* base = &g_Wx[(size_t)(jbase + 2 * j2) * NC + c2];
            float2 r0 = *(const float2*)base;
            float2 r1 = *(const float2*)(base + NC);
            uint2 pk;
            pk.x = pack_bf16(r0.x, r1.x);
            pk.y = pack_bf16(r0.y, r1.y);
            *(uint2*)&WxS[0][j2 * WXS_STRIDE + c2] = pk;
        }
    }
    __syncthreads();

    // ---------------- main loop ----------------
    for (int r = 0; r < NROUND; r++) {
        const int b = r & 1;

        // EARLY: prefetch next round's adj (consumed after the MMA loop)
        int avn[16];
        if (r < NROUND - 1) {
            #pragma unroll
            for (int q = 0; q < 16; q++)
                avn[q] = ldcs_i(&arow[(size_t)q * NN + (r + 1) * JSTEP + lane]);
        }

        // my 8 mask words for this round
        uint32_t aw[4][2];
        #pragma unroll
        for (int mt = 0; mt < 4; mt++) {
            aw[mt][0] = adjW[b][mt * 16 + g];
            aw[mt][1] = adjW[b][mt * 16 + g + 8];
        }

        #pragma unroll
        for (int ks = 0; ks < 2; ks++) {     // two K=16 steps
            const int jq = ks * 8;           // j-pair base within round
            // B fragments (4 n-tiles), conflict-free (banks 8*tig+g)
            uint32_t b0[4], b1[4];
            #pragma unroll
            for (int nt = 0; nt < 4; nt++) {
                b0[nt] = WxS[b][(jq + tig) * WXS_STRIDE + h * OUTF + nt * 8 + g];
                b1[nt] = WxS[b][(jq + tig + 4) * WXS_STRIDE + h * OUTF + nt * 8 + g];
            }
            // ed-side exponential pairs (LDS.64 broadcast within quads)
            const int kb = r * JSTEP + ks * 16 + 2 * tig;
            float2 B0 = *(const float2*)&edB[h][kb];
            float2 B1 = *(const float2*)&edB[h][kb + 8];
            float2 D0 = *(const float2*)&edD[h][kb];
            float2 D1 = *(const float2*)&edD[h][kb + 8];
            const int sh0 = 31 - (ks * 16 + 2 * tig);   // bit j0 -> sign

            #pragma unroll
            for (int mt = 0; mt < 4; mt++) {
                // row g
                float p00 = pmask(eA[mt][0], B0.x, eC[mt][0], D0.x, aw[mt][0], sh0);
                float p01 = pmask(eA[mt][0], B0.y, eC[mt][0], D0.y, aw[mt][0], sh0 - 1);
                float p02 = pmask(eA[mt][0], B1.x, eC[mt][0], D1.x, aw[mt][0], sh0 - 8);
                float p03 = pmask(eA[mt][0], B1.y, eC[mt][0], D1.y, aw[mt][0], sh0 - 9);
                // row g+8
                float p10 = pmask(eA[mt][1], B0.x, eC[mt][1], D0.x, aw[mt][1], sh0);
                float p11 = pmask(eA[mt][1], B0.y, eC[mt][1], D0.y, aw[mt][1], sh0 - 1);
                float p12 = pmask(eA[mt][1], B1.x, eC[mt][1], D1.x, aw[mt][1], sh0 - 8);
                float p13 = pmask(eA[mt][1], B1.y, eC[mt][1], D1.y, aw[mt][1], sh0 - 9);
                uint32_t a0 = pack_bf16(p00, p01);
                uint32_t a1 = pack_bf16(p10, p11);
                uint32_t a2 = pack_bf16(p02, p03);
                uint32_t a3 = pack_bf16(p12, p13);
                // Z from the bf16-rounded P (consistent with the numerator)
                z[mt][0] += (bflo(a0) + bfhi(a0)) + (bflo(a2) + bfhi(a2));
                z[mt][1] += (bflo(a1) + bfhi(a1)) + (bflo(a3) + bfhi(a3));
                #pragma unroll
                for (int nt = 0; nt < 4; nt++)
                    mma16(acc[mt][nt], a0, a1, a2, a3, b0[nt], b1[nt]);
            }
        }

        // LATE: pack prefetched adj + restage Wx pairs into buffer b^1
        if (r < NROUND - 1) {
            #pragma unroll
            for (int q = 0; q < 16; q++) {
                uint32_t m = __ballot_sync(0xffffffffu, avn[q] != 0);
                if (lane == 0) adjW[b ^ 1][w * 16 + q] = m;
            }
            #pragma unroll
            for (int p = 0; p < 8; p++) {
                int idx = t + 128 * p;
                int j2 = idx >> 6, c2 = (idx & 63) << 1;
                const float* base =
                    &g_Wx[(size_t)(jbase + (r + 1) * JSTEP + 2 * j2) * NC + c2];
                float2 r0 = *(const float2*)base;
                float2 r1 = *(const float2*)(base + NC);
                uint2 pk;
                pk.x = pack_bf16(r0.x, r1.x);
                pk.y = pack_bf16(r0.y, r1.y);
                *(uint2*)&WxS[b ^ 1][j2 * WXS_STRIDE + c2] = pk;
            }
        }
        __syncthreads();
    }

    // ---- epilogue: D fragments -> partial numerators; Z reduce ----
    float* np = g_nump[jc];
    #pragma unroll
    for (int mt = 0; mt < 4; mt++) {
        int r0 = ibase + mt * 16 + g;
        #pragma unroll
        for (int nt = 0; nt < 4; nt++) {
            int c = h * OUTF + nt * 8 + tig * 2;
            *(float2*)&np[(size_t)r0 * NC + c] =
                make_float2(acc[mt][nt][0], acc[mt][nt][1]);
            *(float2*)&np[(size_t)(r0 + 8) * NC + c] =
                make_float2(acc[mt][nt][2], acc[mt][nt][3]);
        }
        float z0 = z[mt][0], z1 = z[mt][1];
        z0 += __shfl_xor_sync(0xffffffffu, z0, 1);
        z0 += __shfl_xor_sync(0xffffffffu, z0, 2);
        z1 += __shfl_xor_sync(0xffffffffu, z1, 1);
        z1 += __shfl_xor_sync(0xffffffffu, z1, 2);
        if (tig == 0) {
            g_Zp[jc][(size_t)r0 * NH + h] = z0;
            g_Zp[jc][(size_t)(r0 + 8) * NH + h] = z1;
        }
    }
}

// =====================================================================
// K3: normalize — out = (sum_s num_s) / (sum_s Z_s).
// =====================================================================
__global__ __launch_bounds__(256) void k_norm(float* __restrict__ out) {
    int g = blockIdx.x * 256 + threadIdx.x;
    int i = g >> 5;
    int c4 = (g & 31) << 2;
    int h = c4 >> 5;
    float4 num = make_float4(0.f, 0.f, 0.f, 0.f);
    float Z = 0.f;
    #pragma unroll
    for (int s = 0; s < JSPLIT; s++) {
        float4 v = *(const float4*)&g_nump[s][(size_t)i * NC + c4];
        num.x += v.x; num.y += v.y; num.z += v.z; num.w += v.w;
        Z += g_Zp[s][i * NH + h];
    }
    float inv = 1.f / Z;
    *(float4*)&out[(size_t)i * NC + c4] =
        make_float4(num.x * inv, num.y * inv, num.z * inv, num.w * inv);
}

// =====================================================================
extern "C" void kernel_launch(void* const* d_in, const int* in_sizes, int n_in,
                              void* d_out, int out_size) {
    const float* x = nullptr;
    const int*   adj = nullptr;
    const float* W = nullptr;
    const float* a = nullptr;
    for (int i = 0; i < n_in; i++) {
        switch (in_sizes[i]) {
            case NN * INF_:       x   = (const float*)d_in[i]; break;
            case NN * NN:         adj = (const int*)d_in[i];   break;
            case INF_ * NC:       W   = (const float*)d_in[i]; break;
            case NH * 2 * OUTF:   a   = (const float*)d_in[i]; break;
            default: break;
        }
    }
    float* out = (float*)d_out;

    // k_gemm uses 80 KB dynamic smem: opt-in (host attribute; graph-safe).
    const int gemm_smem = (16384 + 4096) * (int)sizeof(float);  // 81920
    cudaFuncSetAttribute(k_gemm, cudaFuncAttributeMaxDynamicSharedMemorySize,
                         gemm_smem);

    k_gemm<<<NN / 32, 256, gemm_smem>>>(x, W, a);
    dim3 g_attn(JSPLIT, NN / ITILE);   // (8, 64)
    k_attn<<<g_attn, 128>>>(adj);
    k_norm<<<(NN * NC / 4) / 256, 256>>>(out);
    (void)out_size;
}

// round 14
// speedup vs baseline: 1.6421x; 1.0577x over previous
#include <cuda_runtime.h>
#include <cstdint>

// Problem constants (fixed by the reference)
#define NN    4096     // nodes
#define INF_  128      // input features
#define OUTF  32       // output features per head
#define NH    4        // heads
#define NC    128      // NH*OUTF

// Attention tiling
#define ITILE  32                 // i-rows per block (fine quanta for balance)
#define JSPLIT 8                  // j-range splits (additive partial softmax)
#define JCHUNK (NN / JSPLIT)      // 512
#define JSTEP  32                 // j's per round
#define NROUND (JCHUNK / JSTEP)   // 16

#define LOG2E 1.4426950408889634f
#define WXS_STRIDE 136            // 128 + 8 pad (uint32 units)

// ---------------- scratch (device globals; no allocation allowed) ----------------
__device__ __align__(16) float g_Wx[NN * NC];            // 2 MB
__device__ __align__(16) float g_esA[NN * NH];           // e^{es}
__device__ __align__(16) float g_esC[NN * NH];           // e^{0.2 es}
__device__ __align__(16) float g_edB[NN * NH];           // e^{ed}
__device__ __align__(16) float g_edD[NN * NH];           // e^{0.2 ed}
__device__ __align__(16) float g_nump[JSPLIT][NN * NC];  // 16 MB partial numerators
__device__ __align__(16) float g_Zp[JSPLIT][NN * NH];    // partial denominators

// ---------------- helpers ----------------
__device__ __forceinline__ float ex2f(float x) {
    float r;
    asm("ex2.approx.f32 %0, %1;" : "=f"(r) : "f"(x));
    return r;
}
// pack two f32 -> bf16x2 (lo = first k element, hi = second)
__device__ __forceinline__ uint32_t pack_bf16(float lo, float hi) {
    uint32_t r;
    asm("cvt.rn.bf16x2.f32 %0, %1, %2;" : "=r"(r) : "f"(hi), "f"(lo));
    return r;
}
// d = (c >= 0) ? a : b   (int condition — NaN-safe mask select)
__device__ __forceinline__ float slct_i(float a, float b, int c) {
    float d;
    asm("slct.f32.s32 %0, %1, %2, %3;" : "=f"(d) : "f"(a), "f"(b), "r"(c));
    return d;
}
// masked P via max form: exp(leaky(s)) = max(e^s, e^{0.2s}) = max(A*B, C*D)
__device__ __forceinline__ float pmask(float A, float B, float C, float D,
                                       uint32_t aw, int sh) {
    float p = fmaxf(A * B, C * D);
    int r = (int)(aw << sh);                    // mask bit -> sign position
    return slct_i(0.0f, p, r);                  // bit=1 -> p, bit=0 -> 0
}
// bf16x2 halves as floats (for consistent Z accumulation)
__device__ __forceinline__ float bflo(uint32_t pk) {
    return __uint_as_float(pk << 16);
}
__device__ __forceinline__ float bfhi(uint32_t pk) {
    return __uint_as_float(pk & 0xFFFF0000u);
}
// m16n8k16 bf16 HMMA (sm_80+ baseline PTX)
__device__ __forceinline__ void mma16(float* d, uint32_t a0, uint32_t a1,
                                      uint32_t a2, uint32_t a3,
                                      uint32_t b0, uint32_t b1) {
    asm volatile(
        "mma.sync.aligned.m16n8k16.row.col.f32.bf16.bf16.f32 "
        "{%0,%1,%2,%3}, {%4,%5,%6,%7}, {%8,%9}, {%0,%1,%2,%3};"
        : "+f"(d[0]), "+f"(d[1]), "+f"(d[2]), "+f"(d[3])
        : "r"(a0), "r"(a1), "r"(a2), "r"(a3), "r"(b0), "r"(b1));
}
__device__ __forceinline__ int ldcs_i(const int* p) {
    int v;
    asm volatile("ld.global.cs.s32 %0, [%1];" : "=r"(v) : "l"(p));
    return v;
}

// =====================================================================
// K1: Wx = x @ W. 256 threads, 32 rows/block (grid 128), 4 rows x 4 cols
// per thread. Full W staged once (64 KB) + x tile (16 KB): 80 KB dynamic
// smem -> opt-in. Epilogue stores per-(node,head) exponentials
// A=e^es, C=e^{0.2es}, B=e^ed, D=e^{0.2ed}.  (measured 10.1us)
// =====================================================================
__global__ __launch_bounds__(256) void k_gemm(const float* __restrict__ x,
                                              const float* __restrict__ W,
                                              const float* __restrict__ a) {
    extern __shared__ __align__(16) float sm[];
    float* Ws = sm;            // 128*128 floats = 64 KB
    float* xs = sm + 16384;    // 32*128  floats = 16 KB
    const int t = threadIdx.x;
    const int rowbase = blockIdx.x * 32;

    #pragma unroll
    for (int p = 0; p < 16; p++) {
        int idx = t + 256 * p;
        int kr = idx >> 5, c4 = (idx & 31) << 2;
        *(float4*)&Ws[kr * 128 + c4] = *(const float4*)&W[(size_t)kr * NC + c4];
    }
    #pragma unroll
    for (int p = 0; p < 4; p++) {
        int idx = t + 256 * p;
        int r = idx >> 5, c4 = (idx & 31) << 2;
        *(float4*)&xs[r * 128 + c4] =
            *(const float4*)&x[(size_t)(rowbase + r) * INF_ + c4];
    }
    __syncthreads();

    const int cg = t & 31;
    const int rg = t >> 5;     // 0..7, rows rg*4..rg*4+3
    const int c0 = cg << 2;

    float acc[4][4];
    #pragma unroll
    for (int i = 0; i < 4; i++)
        #pragma unroll
        for (int j = 0; j < 4; j++) acc[i][j] = 0.f;

    #pragma unroll 4
    for (int k = 0; k < INF_; k++) {
        float4 w4 = *(const float4*)&Ws[k * 128 + c0];
        #pragma unroll
        for (int rr = 0; rr < 4; rr++) {
            float xv = xs[(rg * 4 + rr) * 128 + k];
            acc[rr][0] += xv * w4.x;
            acc[rr][1] += xv * w4.y;
            acc[rr][2] += xv * w4.z;
            acc[rr][3] += xv * w4.w;
        }
    }

    const int h = cg >> 3;
    const int fbase = c0 & 31;
    #pragma unroll
    for (int rr = 0; rr < 4; rr++) {
        int row = rowbase + rg * 4 + rr;
        *(float4*)&g_Wx[(size_t)row * NC + c0] =
            make_float4(acc[rr][0], acc[rr][1], acc[rr][2], acc[rr][3]);
        float es = 0.f, ed = 0.f;
        #pragma unroll
        for (int q = 0; q < 4; q++) {
            float av = __ldg(&a[h * (2 * OUTF) + fbase + q]);
            float bv = __ldg(&a[h * (2 * OUTF) + OUTF + fbase + q]);
            es += acc[rr][q] * av;
            ed += acc[rr][q] * bv;
        }
        es += __shfl_xor_sync(0xffffffffu, es, 1);
        es += __shfl_xor_sync(0xffffffffu, es, 2);
        es += __shfl_xor_sync(0xffffffffu, es, 4);
        ed += __shfl_xor_sync(0xffffffffu, ed, 1);
        ed += __shfl_xor_sync(0xffffffffu, ed, 2);
        ed += __shfl_xor_sync(0xffffffffu, ed, 4);
        if ((cg & 7) == 0) {
            g_esA[row * NH + h] = ex2f(es * LOG2E);
            g_esC[row * NH + h] = ex2f(0.2f * es * LOG2E);
            g_edB[row * NH + h] = ex2f(ed * LOG2E);
            g_edD[row * NH + h] = ex2f(0.2f * ed * LOG2E);
        }
    }
}

// =====================================================================
// K2: bf16 m16n8k16 HMMA attention aggregation, exp-factorized P
// (max form: P = adj ? max(A_i*B_j, C_i*D_j) : 0).
// Grid (8, 128) = 1024 blocks (fine quanta -> ~99% per-SM HMMA balance).
// Block 128 = 4 warps; warp == head; 32i x 32f per warp over K=512
// (2 m-tiles x 4 n-tiles, acc = 32 regs; launch_bounds(128,4)).
// adj pipeline (prefetch into regs, ballot after MMA) kept.
// Z accumulated from the bf16-ROUNDED P (numerator-consistent).
// =====================================================================
__global__ __launch_bounds__(128, 4) void k_attn(const int* __restrict__ adj) {
    __shared__ __align__(16) uint32_t WxS[2][16 * WXS_STRIDE];  // 17408 B
    __shared__ __align__(16) float edB[NH][JCHUNK];             //  8192 B
    __shared__ __align__(16) float edD[NH][JCHUNK];             //  8192 B
    __shared__ uint32_t adjW[2][ITILE];                         //   256 B

    const int t = threadIdx.x;
    const int w = t >> 5, lane = t & 31;
    const int g = lane >> 2, tig = lane & 3;
    const int h = w;                    // warp == head
    const int ibase = blockIdx.y * ITILE;
    const int jc = blockIdx.x;
    const int jbase = jc * JCHUNK;

    // stage ed-side exponentials, transposed to head-major
    for (int idx = t; idx < JCHUNK; idx += 128) {
        float4 b4 = *(const float4*)&g_edB[(size_t)(jbase + idx) * NH];
        edB[0][idx] = b4.x; edB[1][idx] = b4.y;
        edB[2][idx] = b4.z; edB[3][idx] = b4.w;
        float4 d4 = *(const float4*)&g_edD[(size_t)(jbase + idx) * NH];
        edD[0][idx] = d4.x; edD[1][idx] = d4.y;
        edD[2][idx] = d4.z; edD[3][idx] = d4.w;
    }

    // es-side exponentials for my 4 rows
    float eA[2][2], eC[2][2];
    #pragma unroll
    for (int mt = 0; mt < 2; mt++) {
        eA[mt][0] = g_esA[(size_t)(ibase + mt * 16 + g) * NH + h];
        eA[mt][1] = g_esA[(size_t)(ibase + mt * 16 + g + 8) * NH + h];
        eC[mt][0] = g_esC[(size_t)(ibase + mt * 16 + g) * NH + h];
        eC[mt][1] = g_esC[(size_t)(ibase + mt * 16 + g + 8) * NH + h];
    }

    float acc[2][4][4];
    #pragma unroll
    for (int mt = 0; mt < 2; mt++)
        #pragma unroll
        for (int nt = 0; nt < 4; nt++)
            #pragma unroll
            for (int q = 0; q < 4; q++) acc[mt][nt][q] = 0.f;
    float z[2][2];
    #pragma unroll
    for (int mt = 0; mt < 2; mt++) { z[mt][0] = 0.f; z[mt][1] = 0.f; }

    // adj staging rows for this warp: ibase + w*8 .. +7 (lane = j)
    const int* arow = adj + (size_t)(ibase + w * 8) * NN + jbase;

    // ---------------- prologue: stage round 0 ----------------
    {
        int av[8];
        #pragma unroll
        for (int q = 0; q < 8; q++) av[q] = ldcs_i(&arow[(size_t)q * NN + lane]);
        #pragma unroll
        for (int q = 0; q < 8; q++) {
            uint32_t m = __ballot_sync(0xffffffffu, av[q] != 0);
            if (lane == 0) adjW[0][w * 8 + q] = m;
        }
        #pragma unroll
        for (int p = 0; p < 8; p++) {
            int idx = t + 128 * p;
            int j2 = idx >> 6, c2 = (idx & 63) << 1;
            const float* base = &g_Wx[(size_t)(jbase + 2 * j2) * NC + c2];
            float2 r0 = *(const float2*)base;
            float2 r1 = *(const float2*)(base + NC);
            uint2 pk;
            pk.x = pack_bf16(r0.x, r1.x);
            pk.y = pack_bf16(r0.y, r1.y);
            *(uint2*)&WxS[0][j2 * WXS_STRIDE + c2] = pk;
        }
    }
    __syncthreads();

    // ---------------- main loop ----------------
    for (int r = 0; r < NROUND; r++) {
        const int b = r & 1;

        // EARLY: prefetch next round's adj (consumed after the MMA loop)
        int avn[8];
        if (r < NROUND - 1) {
            #pragma unroll
            for (int q = 0; q < 8; q++)
                avn[q] = ldcs_i(&arow[(size_t)q * NN + (r + 1) * JSTEP + lane]);
        }

        // my 4 mask words for this round
        uint32_t aw[2][2];
        #pragma unroll
        for (int mt = 0; mt < 2; mt++) {
            aw[mt][0] = adjW[b][mt * 16 + g];
            aw[mt][1] = adjW[b][mt * 16 + g + 8];
        }

        #pragma unroll
        for (int ks = 0; ks < 2; ks++) {     // two K=16 steps
            const int jq = ks * 8;           // j-pair base within round
            // B fragments (4 n-tiles), conflict-free (banks 8*tig+g)
            uint32_t b0[4], b1[4];
            #pragma unroll
            for (int nt = 0; nt < 4; nt++) {
                b0[nt] = WxS[b][(jq + tig) * WXS_STRIDE + h * OUTF + nt * 8 + g];
                b1[nt] = WxS[b][(jq + tig + 4) * WXS_STRIDE + h * OUTF + nt * 8 + g];
            }
            // ed-side exponential pairs (LDS.64 broadcast within quads)
            const int kb = r * JSTEP + ks * 16 + 2 * tig;
            float2 B0 = *(const float2*)&edB[h][kb];
            float2 B1 = *(const float2*)&edB[h][kb + 8];
            float2 D0 = *(const float2*)&edD[h][kb];
            float2 D1 = *(const float2*)&edD[h][kb + 8];
            const int sh0 = 31 - (ks * 16 + 2 * tig);   // bit j0 -> sign

            #pragma unroll
            for (int mt = 0; mt < 2; mt++) {
                // row g
                float p00 = pmask(eA[mt][0], B0.x, eC[mt][0], D0.x, aw[mt][0], sh0);
                float p01 = pmask(eA[mt][0], B0.y, eC[mt][0], D0.y, aw[mt][0], sh0 - 1);
                float p02 = pmask(eA[mt][0], B1.x, eC[mt][0], D1.x, aw[mt][0], sh0 - 8);
                float p03 = pmask(eA[mt][0], B1.y, eC[mt][0], D1.y, aw[mt][0], sh0 - 9);
                // row g+8
                float p10 = pmask(eA[mt][1], B0.x, eC[mt][1], D0.x, aw[mt][1], sh0);
                float p11 = pmask(eA[mt][1], B0.y, eC[mt][1], D0.y, aw[mt][1], sh0 - 1);
                float p12 = pmask(eA[mt][1], B1.x, eC[mt][1], D1.x, aw[mt][1], sh0 - 8);
                float p13 = pmask(eA[mt][1], B1.y, eC[mt][1], D1.y, aw[mt][1], sh0 - 9);
                uint32_t a0 = pack_bf16(p00, p01);
                uint32_t a1 = pack_bf16(p10, p11);
                uint32_t a2 = pack_bf16(p02, p03);
                uint32_t a3 = pack_bf16(p12, p13);
                // Z from the bf16-rounded P (consistent with the numerator)
                z[mt][0] += (bflo(a0) + bfhi(a0)) + (bflo(a2) + bfhi(a2));
                z[mt][1] += (bflo(a1) + bfhi(a1)) + (bflo(a3) + bfhi(a3));
                #pragma unroll
                for (int nt = 0; nt < 4; nt++)
                    mma16(acc[mt][nt], a0, a1, a2, a3, b0[nt], b1[nt]);
            }
        }

        // LATE: pack prefetched adj + restage Wx pairs into buffer b^1
        if (r < NROUND - 1) {
            #pragma unroll
            for (int q = 0; q < 8; q++) {
                uint32_t m = __ballot_sync(0xffffffffu, avn[q] != 0);
                if (lane == 0) adjW[b ^ 1][w * 8 + q] = m;
            }
            #pragma unroll
            for (int p = 0; p < 8; p++) {
                int idx = t + 128 * p;
                int j2 = idx >> 6, c2 = (idx & 63) << 1;
                const float* base =
                    &g_Wx[(size_t)(jbase + (r + 1) * JSTEP + 2 * j2) * NC + c2];
                float2 r0 = *(const float2*)base;
                float2 r1 = *(const float2*)(base + NC);
                uint2 pk;
                pk.x = pack_bf16(r0.x, r1.x);
                pk.y = pack_bf16(r0.y, r1.y);
                *(uint2*)&WxS[b ^ 1][j2 * WXS_STRIDE + c2] = pk;
            }
        }
        __syncthreads();
    }

    // ---- epilogue: D fragments -> partial numerators; Z reduce ----
    float* np = g_nump[jc];
    #pragma unroll
    for (int mt = 0; mt < 2; mt++) {
        int r0 = ibase + mt * 16 + g;
        #pragma unroll
        for (int nt = 0; nt < 4; nt++) {
            int c = h * OUTF + nt * 8 + tig * 2;
            *(float2*)&np[(size_t)r0 * NC + c] =
                make_float2(acc[mt][nt][0], acc[mt][nt][1]);
            *(float2*)&np[(size_t)(r0 + 8) * NC + c] =
                make_float2(acc[mt][nt][2], acc[mt][nt][3]);
        }
        float z0 = z[mt][0], z1 = z[mt][1];
        z0 += __shfl_xor_sync(0xffffffffu, z0, 1);
        z0 += __shfl_xor_sync(0xffffffffu, z0, 2);
        z1 += __shfl_xor_sync(0xffffffffu, z1, 1);
        z1 += __shfl_xor_sync(0xffffffffu, z1, 2);
        if (tig == 0) {
            g_Zp[jc][(size_t)r0 * NH + h] = z0;
            g_Zp[jc][(size_t)(r0 + 8) * NH + h] = z1;
        }
    }
}

// =====================================================================
// K3: normalize — out = (sum_s num_s) / (sum_s Z_s).
// =====================================================================
__global__ __launch_bounds__(256) void k_norm(float* __restrict__ out) {
    int g = blockIdx.x * 256 + threadIdx.x;
    int i = g >> 5;
    int c4 = (g & 31) << 2;
    int h = c4 >> 5;
    float4 num = make_float4(0.f, 0.f, 0.f, 0.f);
    float Z = 0.f;
    #pragma unroll
    for (int s = 0; s < JSPLIT; s++) {
        float4 v = *(const float4*)&g_nump[s][(size_t)i * NC + c4];
        num.x += v.x; num.y += v.y; num.z += v.z; num.w += v.w;
        Z += g_Zp[s][i * NH + h];
    }
    float inv = 1.f / Z;
    *(float4*)&out[(size_t)i * NC + c4] =
        make_float4(num.x * inv, num.y * inv, num.z * inv, num.w * inv);
}

// =====================================================================
extern "C" void kernel_launch(void* const* d_in, const int* in_sizes, int n_in,
                              void* d_out, int out_size) {
    const float* x = nullptr;
    const int*   adj = nullptr;
    const float* W = nullptr;
    const float* a = nullptr;
    for (int i = 0; i < n_in; i++) {
        switch (in_sizes[i]) {
            case NN * INF_:       x   = (const float*)d_in[i]; break;
            case NN * NN:         adj = (const int*)d_in[i];   break;
            case INF_ * NC:       W   = (const float*)d_in[i]; break;
            case NH * 2 * OUTF:   a   = (const float*)d_in[i]; break;
            default: break;
        }
    }
    float* out = (float*)d_out;

    // k_gemm uses 80 KB dynamic smem: opt-in (host attribute; graph-safe).
    const int gemm_smem = (16384 + 4096) * (int)sizeof(float);  // 81920
    cudaFuncSetAttribute(k_gemm, cudaFuncAttributeMaxDynamicSharedMemorySize,
                         gemm_smem);

    k_gemm<<<NN / 32, 256, gemm_smem>>>(x, W, a);
    dim3 g_attn(JSPLIT, NN / ITILE);   // (8, 128)
    k_attn<<<g_attn, 128>>>(adj);
    k_norm<<<(NN * NC / 4) / 256, 256>>>(out);
    (void)out_size;
}

// round 15
// speedup vs baseline: 1.8661x; 1.1365x over previous
#include <cuda_runtime.h>
#include <cstdint>

// Problem constants (fixed by the reference)
#define NN    4096     // nodes
#define INF_  128      // input features
#define OUTF  32       // output features per head
#define NH    4        // heads
#define NC    128      // NH*OUTF

// Attention tiling
#define ITILE  32                 // i-rows per block (fine quanta for balance)
#define JSPLIT 8                  // j-range splits (additive partial softmax)
#define JCHUNK (NN / JSPLIT)      // 512
#define JSTEP  32                 // j's per round
#define NROUND (JCHUNK / JSTEP)   // 16

#define LOG2E 1.4426950408889634f
#define WXS_STRIDE 136            // 128 + 8 pad (uint32 units)

// ---------------- scratch (device globals; no allocation allowed) ----------------
// Wx stored ONLY as bf16 j-pair packs: g_WxP[j2*NC + c] = bf16x2(Wx[2j2][c], Wx[2j2+1][c])
__device__ __align__(16) uint32_t g_WxP[(NN / 2) * NC];  // 1 MB
__device__ __align__(16) float g_esA[NN * NH];           // e^{es}
__device__ __align__(16) float g_esC[NN * NH];           // e^{0.2 es}
__device__ __align__(16) float g_edB[NN * NH];           // e^{ed}
__device__ __align__(16) float g_edD[NN * NH];           // e^{0.2 ed}
__device__ __align__(16) float g_nump[JSPLIT][NN * NC];  // 16 MB partial numerators
__device__ __align__(16) float g_Zp[JSPLIT][NN * NH];    // partial denominators

// ---------------- helpers ----------------
__device__ __forceinline__ float ex2f(float x) {
    float r;
    asm("ex2.approx.f32 %0, %1;" : "=f"(r) : "f"(x));
    return r;
}
// pack two f32 -> bf16x2 (lo = first k element, hi = second)
__device__ __forceinline__ uint32_t pack_bf16(float lo, float hi) {
    uint32_t r;
    asm("cvt.rn.bf16x2.f32 %0, %1, %2;" : "=r"(r) : "f"(hi), "f"(lo));
    return r;
}
// d = (c >= 0) ? a : b   (int condition — NaN-safe mask select)
__device__ __forceinline__ float slct_i(float a, float b, int c) {
    float d;
    asm("slct.f32.s32 %0, %1, %2, %3;" : "=f"(d) : "f"(a), "f"(b), "r"(c));
    return d;
}
// masked P via max form: exp(leaky(s)) = max(e^s, e^{0.2s}) = max(A*B, C*D)
__device__ __forceinline__ float pmask(float A, float B, float C, float D,
                                       uint32_t aw, int sh) {
    float p = fmaxf(A * B, C * D);
    int r = (int)(aw << sh);                    // mask bit -> sign position
    return slct_i(0.0f, p, r);                  // bit=1 -> p, bit=0 -> 0
}
// bf16x2 halves as floats (for consistent Z accumulation)
__device__ __forceinline__ float bflo(uint32_t pk) {
    return __uint_as_float(pk << 16);
}
__device__ __forceinline__ float bfhi(uint32_t pk) {
    return __uint_as_float(pk & 0xFFFF0000u);
}
// m16n8k16 bf16 HMMA (sm_80+ baseline PTX)
__device__ __forceinline__ void mma16(float* d, uint32_t a0, uint32_t a1,
                                      uint32_t a2, uint32_t a3,
                                      uint32_t b0, uint32_t b1) {
    asm volatile(
        "mma.sync.aligned.m16n8k16.row.col.f32.bf16.bf16.f32 "
        "{%0,%1,%2,%3}, {%4,%5,%6,%7}, {%8,%9}, {%0,%1,%2,%3};"
        : "+f"(d[0]), "+f"(d[1]), "+f"(d[2]), "+f"(d[3])
        : "r"(a0), "r"(a1), "r"(a2), "r"(a3), "r"(b0), "r"(b1));
}
__device__ __forceinline__ int ldcs_i(const int* p) {
    int v;
    asm volatile("ld.global.cs.s32 %0, [%1];" : "=r"(v) : "l"(p));
    return v;
}

// =====================================================================
// K1: Wx = x @ W. 256 threads, 32 rows/block (grid 128), 4 rows x 4 cols
// per thread. Full W staged once (64 KB) + x tile (16 KB): 80 KB dynamic
// smem -> opt-in. Epilogue packs Wx row-pairs to bf16x2 (g_WxP) and
// stores per-(node,head) exponentials A,C,B,D.
// =====================================================================
__global__ __launch_bounds__(256) void k_gemm(const float* __restrict__ x,
                                              const float* __restrict__ W,
                                              const float* __restrict__ a) {
    extern __shared__ __align__(16) float sm[];
    float* Ws = sm;            // 128*128 floats = 64 KB
    float* xs = sm + 16384;    // 32*128  floats = 16 KB
    const int t = threadIdx.x;
    const int rowbase = blockIdx.x * 32;

    #pragma unroll
    for (int p = 0; p < 16; p++) {
        int idx = t + 256 * p;
        int kr = idx >> 5, c4 = (idx & 31) << 2;
        *(float4*)&Ws[kr * 128 + c4] = *(const float4*)&W[(size_t)kr * NC + c4];
    }
    #pragma unroll
    for (int p = 0; p < 4; p++) {
        int idx = t + 256 * p;
        int r = idx >> 5, c4 = (idx & 31) << 2;
        *(float4*)&xs[r * 128 + c4] =
            *(const float4*)&x[(size_t)(rowbase + r) * INF_ + c4];
    }
    __syncthreads();

    const int cg = t & 31;
    const int rg = t >> 5;     // 0..7, rows rg*4..rg*4+3
    const int c0 = cg << 2;

    float acc[4][4];
    #pragma unroll
    for (int i = 0; i < 4; i++)
        #pragma unroll
        for (int j = 0; j < 4; j++) acc[i][j] = 0.f;

    #pragma unroll 4
    for (int k = 0; k < INF_; k++) {
        float4 w4 = *(const float4*)&Ws[k * 128 + c0];
        #pragma unroll
        for (int rr = 0; rr < 4; rr++) {
            float xv = xs[(rg * 4 + rr) * 128 + k];
            acc[rr][0] += xv * w4.x;
            acc[rr][1] += xv * w4.y;
            acc[rr][2] += xv * w4.z;
            acc[rr][3] += xv * w4.w;
        }
    }

    // ---- pack row-pairs to bf16x2 (rows rg*4+{0,1} and rg*4+{2,3}) ----
    {
        int j2base = (rowbase >> 1) + rg * 2;   // global pair index
        #pragma unroll
        for (int pr = 0; pr < 2; pr++) {
            uint4 pk;
            pk.x = pack_bf16(acc[2 * pr][0], acc[2 * pr + 1][0]);
            pk.y = pack_bf16(acc[2 * pr][1], acc[2 * pr + 1][1]);
            pk.z = pack_bf16(acc[2 * pr][2], acc[2 * pr + 1][2]);
            pk.w = pack_bf16(acc[2 * pr][3], acc[2 * pr + 1][3]);
            *(uint4*)&g_WxP[(size_t)(j2base + pr) * NC + c0] = pk;
        }
    }

    const int h = cg >> 3;
    const int fbase = c0 & 31;
    #pragma unroll
    for (int rr = 0; rr < 4; rr++) {
        int row = rowbase + rg * 4 + rr;
        float es = 0.f, ed = 0.f;
        #pragma unroll
        for (int q = 0; q < 4; q++) {
            float av = __ldg(&a[h * (2 * OUTF) + fbase + q]);
            float bv = __ldg(&a[h * (2 * OUTF) + OUTF + fbase + q]);
            es += acc[rr][q] * av;
            ed += acc[rr][q] * bv;
        }
        es += __shfl_xor_sync(0xffffffffu, es, 1);
        es += __shfl_xor_sync(0xffffffffu, es, 2);
        es += __shfl_xor_sync(0xffffffffu, es, 4);
        ed += __shfl_xor_sync(0xffffffffu, ed, 1);
        ed += __shfl_xor_sync(0xffffffffu, ed, 2);
        ed += __shfl_xor_sync(0xffffffffu, ed, 4);
        if ((cg & 7) == 0) {
            g_esA[row * NH + h] = ex2f(es * LOG2E);
            g_esC[row * NH + h] = ex2f(0.2f * es * LOG2E);
            g_edB[row * NH + h] = ex2f(ed * LOG2E);
            g_edD[row * NH + h] = ex2f(0.2f * ed * LOG2E);
        }
    }
}

// =====================================================================
// K2: bf16 m16n8k16 HMMA attention aggregation, exp-factorized P.
// Grid (8, 128) = 1024 blocks. Block 128 = 4 warps; warp == head;
// 32i x 32f per warp over K=512 (2 m-tiles x 4 n-tiles).
// Wx staging is now a pure uint4 copy from pre-packed g_WxP
// (half the L2 traffic, no cvt in the staging path).
// =====================================================================
__global__ __launch_bounds__(128, 4) void k_attn(const int* __restrict__ adj) {
    __shared__ __align__(16) uint32_t WxS[2][16 * WXS_STRIDE];  // 17408 B
    __shared__ __align__(16) float edB[NH][JCHUNK];             //  8192 B
    __shared__ __align__(16) float edD[NH][JCHUNK];             //  8192 B
    __shared__ uint32_t adjW[2][ITILE];                         //   256 B

    const int t = threadIdx.x;
    const int w = t >> 5, lane = t & 31;
    const int g = lane >> 2, tig = lane & 3;
    const int h = w;                    // warp == head
    const int ibase = blockIdx.y * ITILE;
    const int jc = blockIdx.x;
    const int jbase = jc * JCHUNK;
    const int jb2 = jbase >> 1;         // pair-index base

    // stage ed-side exponentials, transposed to head-major
    for (int idx = t; idx < JCHUNK; idx += 128) {
        float4 b4 = *(const float4*)&g_edB[(size_t)(jbase + idx) * NH];
        edB[0][idx] = b4.x; edB[1][idx] = b4.y;
        edB[2][idx] = b4.z; edB[3][idx] = b4.w;
        float4 d4 = *(const float4*)&g_edD[(size_t)(jbase + idx) * NH];
        edD[0][idx] = d4.x; edD[1][idx] = d4.y;
        edD[2][idx] = d4.z; edD[3][idx] = d4.w;
    }

    // es-side exponentials for my 4 rows
    float eA[2][2], eC[2][2];
    #pragma unroll
    for (int mt = 0; mt < 2; mt++) {
        eA[mt][0] = g_esA[(size_t)(ibase + mt * 16 + g) * NH + h];
        eA[mt][1] = g_esA[(size_t)(ibase + mt * 16 + g + 8) * NH + h];
        eC[mt][0] = g_esC[(size_t)(ibase + mt * 16 + g) * NH + h];
        eC[mt][1] = g_esC[(size_t)(ibase + mt * 16 + g + 8) * NH + h];
    }

    float acc[2][4][4];
    #pragma unroll
    for (int mt = 0; mt < 2; mt++)
        #pragma unroll
        for (int nt = 0; nt < 4; nt++)
            #pragma unroll
            for (int q = 0; q < 4; q++) acc[mt][nt][q] = 0.f;
    float z[2][2];
    #pragma unroll
    for (int mt = 0; mt < 2; mt++) { z[mt][0] = 0.f; z[mt][1] = 0.f; }

    // adj staging rows for this warp: ibase + w*8 .. +7 (lane = j)
    const int* arow = adj + (size_t)(ibase + w * 8) * NN + jbase;

    // ---------------- prologue: stage round 0 ----------------
    {
        int av[8];
        #pragma unroll
        for (int q = 0; q < 8; q++) av[q] = ldcs_i(&arow[(size_t)q * NN + lane]);
        #pragma unroll
        for (int q = 0; q < 8; q++) {
            uint32_t m = __ballot_sync(0xffffffffu, av[q] != 0);
            if (lane == 0) adjW[0][w * 8 + q] = m;
        }
        #pragma unroll
        for (int p = 0; p < 4; p++) {
            int idx = t + 128 * p;              // 0..511 uint4's
            int j2 = idx >> 5, c4 = (idx & 31) << 2;
            uint4 v = *(const uint4*)&g_WxP[(size_t)(jb2 + j2) * NC + c4];
            *(uint4*)&WxS[0][j2 * WXS_STRIDE + c4] = v;
        }
    }
    __syncthreads();

    // ---------------- main loop ----------------
    for (int r = 0; r < NROUND; r++) {
        const int b = r & 1;

        // EARLY: prefetch next round's adj (consumed after the MMA loop)
        int avn[8];
        if (r < NROUND - 1) {
            #pragma unroll
            for (int q = 0; q < 8; q++)
                avn[q] = ldcs_i(&arow[(size_t)q * NN + (r + 1) * JSTEP + lane]);
        }

        // my 4 mask words for this round
        uint32_t aw[2][2];
        #pragma unroll
        for (int mt = 0; mt < 2; mt++) {
            aw[mt][0] = adjW[b][mt * 16 + g];
            aw[mt][1] = adjW[b][mt * 16 + g + 8];
        }

        #pragma unroll
        for (int ks = 0; ks < 2; ks++) {     // two K=16 steps
            const int jq = ks * 8;           // j-pair base within round
            // B fragments (4 n-tiles), conflict-free (banks 8*tig+g)
            uint32_t b0[4], b1[4];
            #pragma unroll
            for (int nt = 0; nt < 4; nt++) {
                b0[nt] = WxS[b][(jq + tig) * WXS_STRIDE + h * OUTF + nt * 8 + g];
                b1[nt] = WxS[b][(jq + tig + 4) * WXS_STRIDE + h * OUTF + nt * 8 + g];
            }
            // ed-side exponential pairs (LDS.64 broadcast within quads)
            const int kb = r * JSTEP + ks * 16 + 2 * tig;
            float2 B0 = *(const float2*)&edB[h][kb];
            float2 B1 = *(const float2*)&edB[h][kb + 8];
            float2 D0 = *(const float2*)&edD[h][kb];
            float2 D1 = *(const float2*)&edD[h][kb + 8];
            const int sh0 = 31 - (ks * 16 + 2 * tig);   // bit j0 -> sign

            #pragma unroll
            for (int mt = 0; mt < 2; mt++) {
                // row g
                float p00 = pmask(eA[mt][0], B0.x, eC[mt][0], D0.x, aw[mt][0], sh0);
                float p01 = pmask(eA[mt][0], B0.y, eC[mt][0], D0.y, aw[mt][0], sh0 - 1);
                float p02 = pmask(eA[mt][0], B1.x, eC[mt][0], D1.x, aw[mt][0], sh0 - 8);
                float p03 = pmask(eA[mt][0], B1.y, eC[mt][0], D1.y, aw[mt][0], sh0 - 9);
                // row g+8
                float p10 = pmask(eA[mt][1], B0.x, eC[mt][1], D0.x, aw[mt][1], sh0);
                float p11 = pmask(eA[mt][1], B0.y, eC[mt][1], D0.y, aw[mt][1], sh0 - 1);
                float p12 = pmask(eA[mt][1], B1.x, eC[mt][1], D1.x, aw[mt][1], sh0 - 8);
                float p13 = pmask(eA[mt][1], B1.y, eC[mt][1], D1.y, aw[mt][1], sh0 - 9);
                uint32_t a0 = pack_bf16(p00, p01);
                uint32_t a1 = pack_bf16(p10, p11);
                uint32_t a2 = pack_bf16(p02, p03);
                uint32_t a3 = pack_bf16(p12, p13);
                // Z from the bf16-rounded P (consistent with the numerator)
                z[mt][0] += (bflo(a0) + bfhi(a0)) + (bflo(a2) + bfhi(a2));
                z[mt][1] += (bflo(a1) + bfhi(a1)) + (bflo(a3) + bfhi(a3));
                #pragma unroll
                for (int nt = 0; nt < 4; nt++)
                    mma16(acc[mt][nt], a0, a1, a2, a3, b0[nt], b1[nt]);
            }
        }

        // LATE: pack prefetched adj + restage Wx pairs into buffer b^1
        if (r < NROUND - 1) {
            #pragma unroll
            for (int q = 0; q < 8; q++) {
                uint32_t m = __ballot_sync(0xffffffffu, avn[q] != 0);
                if (lane == 0) adjW[b ^ 1][w * 8 + q] = m;
            }
            #pragma unroll
            for (int p = 0; p < 4; p++) {
                int idx = t + 128 * p;
                int j2 = idx >> 5, c4 = (idx & 31) << 2;
                uint4 v = *(const uint4*)
                    &g_WxP[(size_t)(jb2 + (r + 1) * 16 + j2) * NC + c4];
                *(uint4*)&WxS[b ^ 1][j2 * WXS_STRIDE + c4] = v;
            }
        }
        __syncthreads();
    }

    // ---- epilogue: D fragments -> partial numerators; Z reduce ----
    float* np = g_nump[jc];
    #pragma unroll
    for (int mt = 0; mt < 2; mt++) {
        int r0 = ibase + mt * 16 + g;
        #pragma unroll
        for (int nt = 0; nt < 4; nt++) {
            int c = h * OUTF + nt * 8 + tig * 2;
            *(float2*)&np[(size_t)r0 * NC + c] =
                make_float2(acc[mt][nt][0], acc[mt][nt][1]);
            *(float2*)&np[(size_t)(r0 + 8) * NC + c] =
                make_float2(acc[mt][nt][2], acc[mt][nt][3]);
        }
        float z0 = z[mt][0], z1 = z[mt][1];
        z0 += __shfl_xor_sync(0xffffffffu, z0, 1);
        z0 += __shfl_xor_sync(0xffffffffu, z0, 2);
        z1 += __shfl_xor_sync(0xffffffffu, z1, 1);
        z1 += __shfl_xor_sync(0xffffffffu, z1, 2);
        if (tig == 0) {
            g_Zp[jc][(size_t)r0 * NH + h] = z0;
            g_Zp[jc][(size_t)(r0 + 8) * NH + h] = z1;
        }
    }
}

// =====================================================================
// K3: normalize — out = (sum_s num_s) / (sum_s Z_s).
// =====================================================================
__global__ __launch_bounds__(256) void k_norm(float* __restrict__ out) {
    int g = blockIdx.x * 256 + threadIdx.x;
    int i = g >> 5;
    int c4 = (g & 31) << 2;
    int h = c4 >> 5;
    float4 num = make_float4(0.f, 0.f, 0.f, 0.f);
    float Z = 0.f;
    #pragma unroll
    for (int s = 0; s < JSPLIT; s++) {
        float4 v = *(const float4*)&g_nump[s][(size_t)i * NC + c4];
        num.x += v.x; num.y += v.y; num.z += v.z; num.w += v.w;
        Z += g_Zp[s][i * NH + h];
    }
    float inv = 1.f / Z;
    *(float4*)&out[(size_t)i * NC + c4] =
        make_float4(num.x * inv, num.y * inv, num.z * inv, num.w * inv);
}

// =====================================================================
extern "C" void kernel_launch(void* const* d_in, const int* in_sizes, int n_in,
                              void* d_out, int out_size) {
    const float* x = nullptr;
    const int*   adj = nullptr;
    const float* W = nullptr;
    const float* a = nullptr;
    for (int i = 0; i < n_in; i++) {
        switch (in_sizes[i]) {
            case NN * INF_:       x   = (const float*)d_in[i]; break;
            case NN * NN:         adj = (const int*)d_in[i];   break;
            case INF_ * NC:       W   = (const float*)d_in[i]; break;
            case NH * 2 * OUTF:   a   = (const float*)d_in[i]; break;
            default: break;
        }
    }
    float* out = (float*)d_out;

    // k_gemm uses 80 KB dynamic smem: opt-in (host attribute; graph-safe).
    const int gemm_smem = (16384 + 4096) * (int)sizeof(float);  // 81920
    cudaFuncSetAttribute(k_gemm, cudaFuncAttributeMaxDynamicSharedMemorySize,
                         gemm_smem);

    k_gemm<<<NN / 32, 256, gemm_smem>>>(x, W, a);
    dim3 g_attn(JSPLIT, NN / ITILE);   // (8, 128)
    k_attn<<<g_attn, 128>>>(adj);
    k_norm<<<(NN * NC / 4) / 256, 256>>>(out);
    (void)out_size;
}